// round 4
// baseline (speedup 1.0000x reference)
#include <cuda_runtime.h>
#include <cuda_bf16.h>
#include <math.h>
#include <float.h>
#include <stdint.h>

// Problem constants
#define BB 16
#define NN 1000
#define EE 4000
#define DD 256
#define NH 4
#define HD 1024
#define LL 64
#define ACT 128
#define OO 256
#define G3 768
#define QKVS_W 4096

// ================= scratch (device globals) =================
__device__ __align__(16) __nv_bfloat16 g_xhi[BB*NN*DD],  g_xlo[BB*NN*DD];
__device__ __align__(16) __nv_bfloat16 g_eahi[BB*EE*DD], g_ealo[BB*EE*DD];
__device__ __align__(16) float g_qkvs[(size_t)BB*NN*QKVS_W];   // q|k|v|skip
__device__ __align__(16) float g_e[(size_t)BB*EE*HD];
__device__ __align__(16) __nv_bfloat16 g_hhi[(size_t)BB*NN*HD], g_hlo[(size_t)BB*NN*HD];
__device__ __align__(16) float g_gr[BB*NN*DD];
__device__ float g_alphaE[BB*EE*NH];
__device__ float g_wcsr[BB*EE*NH];
__device__ int   g_cnt[BB*NN];
__device__ int   g_off[BB*NN];
__device__ int   g_cur[BB*NN];
__device__ int   g_eord[BB*EE];
__device__ __align__(16) __nv_bfloat16 g_invehi[BB*LL*DD], g_invelo[BB*LL*DD];
__device__ __align__(16) __nv_bfloat16 g_invhhi[BB*LL*DD], g_invhlo[BB*LL*DD];
__device__ __align__(16) float g_gx[BB*LL*G3];
__device__ __align__(16) float g_WhhT[DD*G3];
__device__ float g_invvec[BB*OO];
__device__ float g_biasN[QKVS_W];
// bf16 split weight buffers, [N,K] layout (k contiguous)
__device__ __align__(16) __nv_bfloat16 g_bhiN[QKVS_W*DD], g_bloN[QKVS_W*DD];
__device__ __align__(16) __nv_bfloat16 g_bhiE[HD*DD],  g_bloE[HD*DD];
__device__ __align__(16) __nv_bfloat16 g_bhi_w1[DD*HD], g_blo_w1[DD*HD];
__device__ __align__(16) __nv_bfloat16 g_bhi_wp[DD*DD], g_blo_wp[DD*DD];
__device__ __align__(16) __nv_bfloat16 g_bhi_ih[G3*DD], g_blo_ih[G3*DD];

// ================= helpers =================
__device__ __forceinline__ uint32_t smem_to_u32(const void* smem_ptr) {
    uint32_t addr;
    asm("{ .reg .u64 tmp; cvta.to.shared.u64 tmp, %1; cvt.u32.u64 %0, tmp; }"
        : "=r"(addr) : "l"(smem_ptr));
    return addr;
}
__device__ __forceinline__ void ldsm4(uint32_t r[4], uint32_t addr) {
    asm volatile("ldmatrix.sync.aligned.m8n8.x4.shared.b16 {%0,%1,%2,%3}, [%4];"
        : "=r"(r[0]), "=r"(r[1]), "=r"(r[2]), "=r"(r[3]) : "r"(addr));
}
__device__ __forceinline__ void mma16816(float c[4], uint32_t a0, uint32_t a1,
                                         uint32_t a2, uint32_t a3,
                                         uint32_t b0, uint32_t b1) {
    asm volatile(
        "mma.sync.aligned.m16n8k16.row.col.f32.bf16.bf16.f32 "
        "{%0,%1,%2,%3}, {%4,%5,%6,%7}, {%8,%9}, {%0,%1,%2,%3};"
        : "+f"(c[0]), "+f"(c[1]), "+f"(c[2]), "+f"(c[3])
        : "r"(a0), "r"(a1), "r"(a2), "r"(a3), "r"(b0), "r"(b1));
}
__device__ __forceinline__ void cpasync16(uint32_t dst, const void* src) {
    asm volatile("cp.async.cg.shared.global [%0], [%1], 16;" :: "r"(dst), "l"(src));
}
__device__ __forceinline__ void cp_commit() {
    asm volatile("cp.async.commit_group;");
}
template<int N> __device__ __forceinline__ void cp_wait() {
    asm volatile("cp.async.wait_group %0;" :: "n"(N));
}
__device__ __forceinline__ void split2(float a, float b, uint32_t& hw, uint32_t& lw) {
    __nv_bfloat162 hp = __floats2bfloat162_rn(a, b);
    float2 hf = __bfloat1622float2(hp);
    __nv_bfloat162 lp = __floats2bfloat162_rn(a - hf.x, b - hf.y);
    hw = *reinterpret_cast<uint32_t*>(&hp);
    lw = *reinterpret_cast<uint32_t*>(&lp);
}

// ================= gathers / conversions =================
__global__ void gather_split_k(__nv_bfloat16* __restrict__ hi, __nv_bfloat16* __restrict__ lo,
                               const float* __restrict__ emb, const int* __restrict__ idx) {
    int row = blockIdx.x, t = threadIdx.x;
    int tok = idx[row];
    float f = emb[(size_t)tok*DD + t];
    __nv_bfloat16 h = __float2bfloat16_rn(f);
    hi[(size_t)row*DD + t] = h;
    lo[(size_t)row*DD + t] = __float2bfloat16_rn(f - __bfloat162float(h));
}
// strided relu + split: in[row*lda + cOff + col] -> hi/lo [row*C + col]
__global__ void relu_split_k(const float* __restrict__ in, __nv_bfloat16* __restrict__ hi,
                             __nv_bfloat16* __restrict__ lo, int lda, int cOff, int C) {
    int row = blockIdx.x;
    int col = blockIdx.y * 256 + threadIdx.x;
    float f = fmaxf(in[(size_t)row*lda + cOff + col], 0.f);
    __nv_bfloat16 h = __float2bfloat16_rn(f);
    hi[(size_t)row*C + col] = h;
    lo[(size_t)row*C + col] = __float2bfloat16_rn(f - __bfloat162float(h));
}
__global__ void transpose_768x256_k(float* __restrict__ out, const float* __restrict__ in) {
    int g = blockIdx.x, j = threadIdx.x;
    out[j*G3 + g] = in[g*DD + j];
}
// W[K,N] fp32 -> Bhi/Blo [N,K] bf16
__global__ void convWT_k(const float* __restrict__ W, __nv_bfloat16* __restrict__ bhi,
                         __nv_bfloat16* __restrict__ blo, int K, int N) {
    int k = blockIdx.x;
    for (int n = threadIdx.x; n < N; n += blockDim.x) {
        float f = W[(size_t)k*N + n];
        __nv_bfloat16 h = __float2bfloat16_rn(f);
        bhi[(size_t)n*K + k] = h;
        blo[(size_t)n*K + k] = __float2bfloat16_rn(f - __bfloat162float(h));
    }
}
__global__ void convWN_k(const float* __restrict__ W, __nv_bfloat16* __restrict__ bhi,
                         __nv_bfloat16* __restrict__ blo, int total) {
    int i = blockIdx.x * blockDim.x + threadIdx.x;
    if (i >= total) return;
    float f = W[i];
    __nv_bfloat16 h = __float2bfloat16_rn(f);
    bhi[i] = h;
    blo[i] = __float2bfloat16_rn(f - __bfloat162float(h));
}
__global__ void biascat_k(const float* __restrict__ b0, const float* __restrict__ b1,
                          const float* __restrict__ b2, const float* __restrict__ b3,
                          float* __restrict__ o) {
    int t = blockIdx.x * 256 + threadIdx.x;
    const float* src = (t < 1024) ? b0 : (t < 2048) ? b1 : (t < 3072) ? b2 : b3;
    o[t] = src[t & 1023];
}

// ================= mma.sync bf16x3 GEMM (pre-split A and B) =================
// C[M,N] = act(A@B^T + bias); A hi/lo bf16 [M,K], B hi/lo bf16 [N,K]. K mult of 32.
// CTA 128x128, 8 warps, warp tile 64x32. cp.async 4-stage pipeline.
#define KC 32
#define RSB 80
#define STG_A_HI 0
#define STG_A_LO 10240
#define STG_B_HI 20480
#define STG_B_LO 30720
#define STAGE_SZ 40960
#define NSTAGE 4
#define GEMM_SMEM (NSTAGE*STAGE_SZ)

template<int CRELU, int HASBIAS, int OUTSPLIT>
__global__ __launch_bounds__(256, 1) void mmagemm_k(
    const __nv_bfloat16* __restrict__ Ahi, const __nv_bfloat16* __restrict__ Alo,
    const __nv_bfloat16* __restrict__ Bhi, const __nv_bfloat16* __restrict__ Blo,
    const float* __restrict__ bias, float* __restrict__ C,
    __nv_bfloat16* __restrict__ Chi, __nv_bfloat16* __restrict__ Clo,
    int Nld, int K) {
    extern __shared__ char smc[];
    const uint32_t smb = smem_to_u32(smc);
    const int t = threadIdx.x, lane = t & 31, warp = t >> 5;
    const int bm = blockIdx.y * 128, bn = blockIdx.x * 128;
    const int wm = (warp >> 2) * 64, wn = (warp & 3) * 32;

    const int fr = t >> 1, fk = (t & 1) * 16;
    const __nv_bfloat16* Ah = Ahi + (size_t)(bm + fr) * K + fk;
    const __nv_bfloat16* Al = Alo + (size_t)(bm + fr) * K + fk;
    const __nv_bfloat16* Bh = Bhi + (size_t)(bn + fr) * K + fk;
    const __nv_bfloat16* Bl = Blo + (size_t)(bn + fr) * K + fk;
    const uint32_t fillOff = smb + (uint32_t)(fr * RSB + fk * 2);

    const uint32_t aBase = smb + (uint32_t)(wm + (lane & 15)) * RSB + (uint32_t)(lane >> 4) * 16;
    const uint32_t bBase = smb + (uint32_t)(wn + ((lane >> 4) << 3) + (lane & 7)) * RSB
                               + (uint32_t)((lane >> 3) & 1) * 16;

    float acc[4][4][4];
#pragma unroll
    for (int i = 0; i < 4; i++)
#pragma unroll
        for (int j = 0; j < 4; j++)
#pragma unroll
            for (int k = 0; k < 4; k++) acc[i][j][k] = 0.f;

    const int NC = K / KC;

    // prologue: fill stages 0..NSTAGE-2
#pragma unroll
    for (int c = 0; c < NSTAGE - 1; c++) {
        uint32_t d = fillOff + (uint32_t)(c * STAGE_SZ);
        const __nv_bfloat16* a0 = Ah + c * KC;
        const __nv_bfloat16* a1 = Al + c * KC;
        const __nv_bfloat16* b0 = Bh + c * KC;
        const __nv_bfloat16* b1 = Bl + c * KC;
        cpasync16(d + STG_A_HI,      a0);
        cpasync16(d + STG_A_HI + 16, a0 + 8);
        cpasync16(d + STG_A_LO,      a1);
        cpasync16(d + STG_A_LO + 16, a1 + 8);
        cpasync16(d + STG_B_HI,      b0);
        cpasync16(d + STG_B_HI + 16, b0 + 8);
        cpasync16(d + STG_B_LO,      b1);
        cpasync16(d + STG_B_LO + 16, b1 + 8);
        cp_commit();
    }

    for (int c = 0; c < NC; c++) {
        cp_wait<NSTAGE - 2>();
        __syncthreads();
        const uint32_t stg = (uint32_t)((c & (NSTAGE - 1)) * STAGE_SZ);
#pragma unroll
        for (int ks = 0; ks < 2; ks++) {
            const uint32_t kb = (uint32_t)(ks * 32);
#pragma unroll
            for (int pass = 0; pass < 3; pass++) {
                const uint32_t selA = (pass == 1) ? STG_A_LO : STG_A_HI;
                const uint32_t selB = (pass == 2) ? STG_B_LO : STG_B_HI;
                uint32_t ar[4][4];
#pragma unroll
                for (int mi = 0; mi < 4; mi++)
                    ldsm4(ar[mi], aBase + stg + selA + (uint32_t)(mi * 16 * RSB) + kb);
                uint32_t br[2][4];
#pragma unroll
                for (int nb = 0; nb < 2; nb++)
                    ldsm4(br[nb], bBase + stg + selB + (uint32_t)(nb * 16 * RSB) + kb);
#pragma unroll
                for (int mi = 0; mi < 4; mi++)
#pragma unroll
                    for (int ni = 0; ni < 4; ni++)
                        mma16816(acc[mi][ni], ar[mi][0], ar[mi][1], ar[mi][2], ar[mi][3],
                                 br[ni>>1][(ni&1)*2], br[ni>>1][(ni&1)*2+1]);
            }
        }
        __syncthreads();
        const int nx = c + NSTAGE - 1;
        if (nx < NC) {
            uint32_t d = fillOff + (uint32_t)((nx & (NSTAGE - 1)) * STAGE_SZ);
            const __nv_bfloat16* a0 = Ah + nx * KC;
            const __nv_bfloat16* a1 = Al + nx * KC;
            const __nv_bfloat16* b0 = Bh + nx * KC;
            const __nv_bfloat16* b1 = Bl + nx * KC;
            cpasync16(d + STG_A_HI,      a0);
            cpasync16(d + STG_A_HI + 16, a0 + 8);
            cpasync16(d + STG_A_LO,      a1);
            cpasync16(d + STG_A_LO + 16, a1 + 8);
            cpasync16(d + STG_B_HI,      b0);
            cpasync16(d + STG_B_HI + 16, b0 + 8);
            cpasync16(d + STG_B_LO,      b1);
            cpasync16(d + STG_B_LO + 16, b1 + 8);
        }
        cp_commit();
    }

    // ---- epilogue ----
#pragma unroll
    for (int mi = 0; mi < 4; mi++) {
        const int r0 = bm + wm + mi*16 + (lane >> 2);
#pragma unroll
        for (int ni = 0; ni < 4; ni++) {
            const int col = bn + wn + ni*8 + (lane & 3)*2;
            float bx = 0.f, by = 0.f;
            if (HASBIAS) { bx = bias[col]; by = bias[col+1]; }
            float v0 = acc[mi][ni][0] + bx, v1 = acc[mi][ni][1] + by;
            float v2 = acc[mi][ni][2] + bx, v3 = acc[mi][ni][3] + by;
            if (CRELU) {
                v0 = fmaxf(v0, 0.f); v1 = fmaxf(v1, 0.f);
                v2 = fmaxf(v2, 0.f); v3 = fmaxf(v3, 0.f);
            }
            if (OUTSPLIT) {
                uint32_t hw0, lw0, hw1, lw1;
                split2(v0, v1, hw0, lw0);
                split2(v2, v3, hw1, lw1);
                *(uint32_t*)(Chi + (size_t)r0 * Nld + col) = hw0;
                *(uint32_t*)(Clo + (size_t)r0 * Nld + col) = lw0;
                *(uint32_t*)(Chi + (size_t)(r0+8) * Nld + col) = hw1;
                *(uint32_t*)(Clo + (size_t)(r0+8) * Nld + col) = lw1;
            } else {
                *(float2*)(C + (size_t)r0 * Nld + col) = make_float2(v0, v1);
                *(float2*)(C + (size_t)(r0+8) * Nld + col) = make_float2(v2, v3);
            }
        }
    }
}

// ================= CSR build over dst =================
__global__ void zero_cnt_k() {
    int i = blockIdx.x * blockDim.x + threadIdx.x;
    if (i < BB*NN) g_cnt[i] = 0;
}
__global__ void count_k(const int* __restrict__ ei) {
    int i = blockIdx.x * blockDim.x + threadIdx.x;
    if (i >= BB*EE) return;
    int b = i / EE, e = i % EE;
    int dst = ei[(b*2 + 1)*EE + e];
    atomicAdd(&g_cnt[b*NN + dst], 1);
}
__global__ void scan_k() {
    int b = blockIdx.x;
    if (threadIdx.x == 0) {
        int run = 0;
        for (int n = 0; n < NN; n++) {
            g_off[b*NN + n] = run;
            g_cur[b*NN + n] = run;
            run += g_cnt[b*NN + n];
        }
    }
}
__global__ void fill_k(const int* __restrict__ ei) {
    int i = blockIdx.x * blockDim.x + threadIdx.x;
    if (i >= BB*EE) return;
    int b = i / EE, e = i % EE;
    int dst = ei[(b*2 + 1)*EE + e];
    int pos = atomicAdd(&g_cur[b*NN + dst], 1);
    g_eord[b*EE + pos] = e;
}

// ================= attention (3 parallel kernels) =================
// pass 1: per-(b,edge,head) warp computes logit
__global__ void attn_alpha_k(const int* __restrict__ ei) {
    int g = blockIdx.x * 4 + (threadIdx.x >> 5);
    int lane = threadIdx.x & 31;
    if (g >= BB*EE*NH) return;
    int h = g & 3, be = g >> 2;
    int b = be / EE, e = be - b * EE;
    int src = ei[(b*2)*EE + e], dst = ei[(b*2 + 1)*EE + e];
    const float* qp = g_qkvs + (size_t)(b*NN + dst)*QKVS_W + h*DD;
    const float* kp = g_qkvs + (size_t)(b*NN + src)*QKVS_W + HD + h*DD;
    const float* ep = g_e    + (size_t)be*HD + h*DD;
    float acc = 0.f;
#pragma unroll
    for (int r = 0; r < 8; r++) {
        int d = lane + 32*r;
        acc += qp[d] * (kp[d] + ep[d]);
    }
#pragma unroll
    for (int d = 16; d; d >>= 1) acc += __shfl_xor_sync(0xffffffffu, acc, d);
    if (lane == 0) g_alphaE[be*NH + h] = acc * 0.0625f;
}
// pass 2: per-(b,node,head) thread computes softmax weights into CSR order
__global__ void attn_soft_k() {
    int g = blockIdx.x * blockDim.x + threadIdx.x;
    if (g >= BB*NN*NH) return;
    int h = g & 3, bn = g >> 2;
    int deg = g_cnt[bn];
    if (deg == 0) return;
    int off = g_off[bn];
    int b = bn / NN;
    float m = -3.0e38f;
    for (int i = 0; i < deg; i++) {
        int e = g_eord[b*EE + off + i];
        m = fmaxf(m, g_alphaE[(b*EE + e)*NH + h]);
    }
    float s = 0.f;
    for (int i = 0; i < deg; i++) {
        int e = g_eord[b*EE + off + i];
        float w = expf(g_alphaE[(b*EE + e)*NH + h] - m);
        s += w;
        g_wcsr[(b*EE + off + i)*NH + h] = w;
    }
    float inv_s = 1.f / s;
    for (int i = 0; i < deg; i++)
        g_wcsr[(b*EE + off + i)*NH + h] *= inv_s;
}
// pass 3: per-(b,node,head) warp aggregates, adds into skip section of qkvs
__global__ void attn_agg_k(const int* __restrict__ ei) {
    int g = blockIdx.x * 4 + (threadIdx.x >> 5);
    int lane = threadIdx.x & 31;
    if (g >= BB*NN*NH) return;
    int h = g & 3, bn = g >> 2;
    int deg = g_cnt[bn];
    if (deg == 0) return;
    int off = g_off[bn];
    int b = bn / NN;
    float o[8];
#pragma unroll
    for (int r = 0; r < 8; r++) o[r] = 0.f;
    for (int i = 0; i < deg; i++) {
        int e = g_eord[b*EE + off + i];
        int src = ei[(b*2)*EE + e];
        float w = g_wcsr[(b*EE + off + i)*NH + h];
        const float* vp = g_qkvs + (size_t)(b*NN + src)*QKVS_W + 2*HD + h*DD;
        const float* ep = g_e    + (size_t)(b*EE + e)*HD + h*DD;
#pragma unroll
        for (int r = 0; r < 8; r++) {
            int d = lane + 32*r;
            o[r] += w * (vp[d] + ep[d]);
        }
    }
    float* hp = g_qkvs + (size_t)bn*QKVS_W + 3*HD + h*DD;
#pragma unroll
    for (int r = 0; r < 8; r++) hp[lane + 32*r] += o[r];
}

// ================= inv path =================
__global__ void mixed_inv_split_k(const int* __restrict__ tok, const int* __restrict__ nod,
                                  const float* __restrict__ emb) {
    int row = blockIdx.x, t = threadIdx.x;
    int b = row / LL;
    int tk = tok[row], nd = nod[row];
    float f = emb[(size_t)tk*DD + t] + g_gr[(size_t)(b*NN + nd)*DD + t];
    __nv_bfloat16 h = __float2bfloat16_rn(f);
    g_invehi[(size_t)row*DD + t] = h;
    g_invelo[(size_t)row*DD + t] = __float2bfloat16_rn(f - __bfloat162float(h));
}

__global__ void gru_k(const float* __restrict__ b_hh) {
    __shared__ float hs[256];
    __shared__ float ghs[768];
    int b = blockIdx.x, t = threadIdx.x;
    if (t < 256) hs[t] = 0.f;
    float bh = b_hh[t];
    __syncthreads();
    for (int l = 0; l < LL; l++) {
        float acc = bh;
        const float* w = g_WhhT + t;
#pragma unroll 8
        for (int j = 0; j < 256; j++) acc += hs[j] * w[(size_t)j * G3];
        ghs[t] = acc;
        __syncthreads();
        float hn = 0.f;
        if (t < 256) {
            const float* g = g_gx + (size_t)(b*LL + l)*G3;
            float r = 1.f / (1.f + expf(-(g[t]       + ghs[t])));
            float z = 1.f / (1.f + expf(-(g[256 + t] + ghs[256 + t])));
            float c = tanhf(g[512 + t] + r * ghs[512 + t]);
            hn = (1.f - z) * c + z * hs[t];
        }
        __syncthreads();
        if (t < 256) hs[t] = hn;
        __syncthreads();
    }
    if (t < 256) g_invvec[b*OO + t] = hs[t];
}

// ================= scoring =================
__global__ void score_k(const float* __restrict__ Wap, const float* __restrict__ bap,
                        const float* __restrict__ Wab, const float* __restrict__ bab,
                        const int* __restrict__ aa_token, const int* __restrict__ aa_node,
                        const float* __restrict__ mask, const float* __restrict__ emb,
                        float* __restrict__ out) {
    __shared__ float invs[256];
    __shared__ float u[256];
    __shared__ float red[256];
    int b = blockIdx.x, t = threadIdx.x;
    int warp = t >> 5, lane = t & 31;
    invs[t] = g_invvec[b*OO + t];
    __syncthreads();
    for (int d = warp*32; d < warp*32 + 32; d++) {
        float acc = 0.f;
#pragma unroll
        for (int r = 0; r < 8; r++) {
            int o = lane + 32*r;
            acc += Wap[(size_t)d*OO + o] * invs[o];
        }
#pragma unroll
        for (int dd = 16; dd; dd >>= 1) acc += __shfl_xor_sync(0xffffffffu, acc, dd);
        if (lane == 0) u[d] = acc + Wab[d];
    }
    red[t] = bap[t] * invs[t];
    __syncthreads();
    for (int s = 128; s; s >>= 1) {
        if (t < s) red[t] += red[t + s];
        __syncthreads();
    }
    float cb = red[0] + bab[0];
    for (int a = warp; a < ACT; a += 8) {
        int tok = aa_token[b*ACT + a], nod = aa_node[b*ACT + a];
        const float* er = emb + (size_t)tok*DD;
        const float* gg = g_gr + (size_t)(b*NN + nod)*DD;
        float acc = 0.f;
#pragma unroll
        for (int r = 0; r < 8; r++) {
            int d = lane + 32*r;
            acc += (er[d] + gg[d]) * u[d];
        }
#pragma unroll
        for (int dd = 16; dd; dd >>= 1) acc += __shfl_xor_sync(0xffffffffu, acc, dd);
        if (lane == 0) {
            float mk = mask[b*ACT + a];
            float lm = fmaxf(logf(mk), -FLT_MAX);
            out[b*ACT + a] = acc + cb + lm;
        }
    }
}

// ================= host launcher =================
extern "C" void kernel_launch(void* const* d_in, const int* in_sizes, int n_in,
                              void* d_out, int out_size) {
    const int*   node_tokens = (const int*)d_in[0];
    const int*   edge_tokens = (const int*)d_in[1];
    const int*   edge_index  = (const int*)d_in[2];
    const int*   inv_token   = (const int*)d_in[3];
    const int*   inv_node    = (const int*)d_in[4];
    const int*   aa_token    = (const int*)d_in[5];
    const int*   aa_node     = (const int*)d_in[6];
    const float* action_mask = (const float*)d_in[7];
    const float* emb         = (const float*)d_in[8];
    const float* Wq  = (const float*)d_in[9];
    const float* bq  = (const float*)d_in[10];
    const float* Wk  = (const float*)d_in[11];
    const float* bk  = (const float*)d_in[12];
    const float* Wv  = (const float*)d_in[13];
    const float* bv  = (const float*)d_in[14];
    const float* We  = (const float*)d_in[15];
    const float* Wsk = (const float*)d_in[16];
    const float* bsk = (const float*)d_in[17];
    const float* W1  = (const float*)d_in[18];
    const float* b1  = (const float*)d_in[19];
    const float* Wp  = (const float*)d_in[20];
    const float* bp  = (const float*)d_in[21];
    const float* W_ih = (const float*)d_in[22];
    const float* W_hh = (const float*)d_in[23];
    const float* b_ih = (const float*)d_in[24];
    const float* b_hh = (const float*)d_in[25];
    const float* Wab = (const float*)d_in[26];
    const float* bab = (const float*)d_in[27];
    const float* Wap = (const float*)d_in[28];
    const float* bap = (const float*)d_in[29];
    float* out = (float*)d_out;

    void* p;
    __nv_bfloat16 *xhi, *xlo, *eahi, *ealo, *hhi, *hlo, *invehi, *invelo, *invhhi, *invhlo;
    __nv_bfloat16 *bhiN, *bloN, *bhiE, *bloE, *bh1, *bl1, *bhp, *blp, *bhih, *blih;
    float *qkvs, *e_, *gr_, *gx_, *WhhT_, *biasN;
    cudaGetSymbolAddress(&p, g_xhi);    xhi = (__nv_bfloat16*)p;
    cudaGetSymbolAddress(&p, g_xlo);    xlo = (__nv_bfloat16*)p;
    cudaGetSymbolAddress(&p, g_eahi);   eahi = (__nv_bfloat16*)p;
    cudaGetSymbolAddress(&p, g_ealo);   ealo = (__nv_bfloat16*)p;
    cudaGetSymbolAddress(&p, g_qkvs);   qkvs = (float*)p;
    cudaGetSymbolAddress(&p, g_e);      e_ = (float*)p;
    cudaGetSymbolAddress(&p, g_hhi);    hhi = (__nv_bfloat16*)p;
    cudaGetSymbolAddress(&p, g_hlo);    hlo = (__nv_bfloat16*)p;
    cudaGetSymbolAddress(&p, g_gr);     gr_ = (float*)p;
    cudaGetSymbolAddress(&p, g_invehi); invehi = (__nv_bfloat16*)p;
    cudaGetSymbolAddress(&p, g_invelo); invelo = (__nv_bfloat16*)p;
    cudaGetSymbolAddress(&p, g_invhhi); invhhi = (__nv_bfloat16*)p;
    cudaGetSymbolAddress(&p, g_invhlo); invhlo = (__nv_bfloat16*)p;
    cudaGetSymbolAddress(&p, g_gx);     gx_ = (float*)p;
    cudaGetSymbolAddress(&p, g_WhhT);   WhhT_ = (float*)p;
    cudaGetSymbolAddress(&p, g_biasN);  biasN = (float*)p;
    cudaGetSymbolAddress(&p, g_bhiN);   bhiN = (__nv_bfloat16*)p;
    cudaGetSymbolAddress(&p, g_bloN);   bloN = (__nv_bfloat16*)p;
    cudaGetSymbolAddress(&p, g_bhiE);   bhiE = (__nv_bfloat16*)p;
    cudaGetSymbolAddress(&p, g_bloE);   bloE = (__nv_bfloat16*)p;
    cudaGetSymbolAddress(&p, g_bhi_w1); bh1 = (__nv_bfloat16*)p;
    cudaGetSymbolAddress(&p, g_blo_w1); bl1 = (__nv_bfloat16*)p;
    cudaGetSymbolAddress(&p, g_bhi_wp); bhp = (__nv_bfloat16*)p;
    cudaGetSymbolAddress(&p, g_blo_wp); blp = (__nv_bfloat16*)p;
    cudaGetSymbolAddress(&p, g_bhi_ih); bhih = (__nv_bfloat16*)p;
    cudaGetSymbolAddress(&p, g_blo_ih); blih = (__nv_bfloat16*)p;

    cudaFuncSetAttribute(mmagemm_k<0,1,0>, cudaFuncAttributeMaxDynamicSharedMemorySize, GEMM_SMEM);
    cudaFuncSetAttribute(mmagemm_k<0,0,0>, cudaFuncAttributeMaxDynamicSharedMemorySize, GEMM_SMEM);
    cudaFuncSetAttribute(mmagemm_k<1,1,0>, cudaFuncAttributeMaxDynamicSharedMemorySize, GEMM_SMEM);
    cudaFuncSetAttribute(mmagemm_k<1,1,1>, cudaFuncAttributeMaxDynamicSharedMemorySize, GEMM_SMEM);

    // 1. gathers + weight prep
    gather_split_k<<<BB*NN, 256>>>(xhi, xlo, emb, node_tokens);
    gather_split_k<<<BB*EE, 256>>>(eahi, ealo, emb, edge_tokens);
    transpose_768x256_k<<<G3, 256>>>(WhhT_, W_hh);
    convWT_k<<<DD, 256>>>(Wq,  bhiN + 0*HD*DD/1, bloN + 0,           DD, HD);
    convWT_k<<<DD, 256>>>(Wk,  bhiN + 1024*DD,   bloN + 1024*DD,     DD, HD);
    convWT_k<<<DD, 256>>>(Wv,  bhiN + 2048*DD,   bloN + 2048*DD,     DD, HD);
    convWT_k<<<DD, 256>>>(Wsk, bhiN + 3072*DD,   bloN + 3072*DD,     DD, HD);
    convWT_k<<<DD, 256>>>(We,  bhiE, bloE, DD, HD);
    convWT_k<<<HD, 256>>>(W1,  bh1, bl1, HD, DD);
    convWT_k<<<DD, 256>>>(Wp,  bhp, blp, DD, DD);
    convWN_k<<<(G3*DD + 255)/256, 256>>>(W_ih, bhih, blih, G3*DD);
    biascat_k<<<16, 256>>>(bq, bk, bv, bsk, biasN);

    // 2. combined node projections: [16000,256] @ [256,4096] -> qkvs
    dim3 gproj(QKVS_W/128, (BB*NN)/128);
    mmagemm_k<0,1,0><<<gproj, 256, GEMM_SMEM>>>(xhi, xlo, bhiN, bloN, biasN,
                                                qkvs, nullptr, nullptr, QKVS_W, DD);

    // 3. edge projection: [64000,256] @ [256,1024]
    dim3 gedge(HD/128, (BB*EE)/128);
    mmagemm_k<0,0,0><<<gedge, 256, GEMM_SMEM>>>(eahi, ealo, bhiE, bloE, nullptr,
                                                e_, nullptr, nullptr, HD, DD);

    // 4. CSR over dst
    zero_cnt_k<<<(BB*NN + 255)/256, 256>>>();
    count_k<<<(BB*EE + 255)/256, 256>>>(edge_index);
    scan_k<<<BB, 32>>>();
    fill_k<<<(BB*EE + 255)/256, 256>>>(edge_index);

    // 5. attention
    attn_alpha_k<<<(BB*EE*NH + 3)/4, 128>>>(edge_index);
    attn_soft_k<<<(BB*NN*NH + 255)/256, 256>>>();
    attn_agg_k<<<(BB*NN*NH + 3)/4, 128>>>(edge_index);

    // 6. graph_repr = relu(relu(h)@W1 + b1)
    relu_split_k<<<dim3(BB*NN, HD/256), 256>>>(qkvs, hhi, hlo, QKVS_W, 3*HD, HD);
    dim3 ggr(DD/128, (BB*NN)/128);
    mmagemm_k<1,1,0><<<ggr, 256, GEMM_SMEM>>>(hhi, hlo, bh1, bl1, b1,
                                              gr_, nullptr, nullptr, DD, HD);

    // 7. inv path
    mixed_inv_split_k<<<BB*LL, 256>>>(inv_token, inv_node, emb);
    dim3 ginv(DD/128, (BB*LL)/128);
    mmagemm_k<1,1,1><<<ginv, 256, GEMM_SMEM>>>(invehi, invelo, bhp, blp, bp,
                                               nullptr, invhhi, invhlo, DD, DD);
    dim3 ggx(G3/128, (BB*LL)/128);
    mmagemm_k<0,1,0><<<ggx, 256, GEMM_SMEM>>>(invhhi, invhlo, bhih, blih, b_ih,
                                              gx_, nullptr, nullptr, G3, DD);
    gru_k<<<BB, 768>>>(b_hh);

    // 8. scores
    score_k<<<BB, 256>>>(Wap, bap, Wab, bab, aa_token, aa_node, action_mask, emb, out);
    (void)in_sizes; (void)n_in; (void)out_size;
}

// round 7
// speedup vs baseline: 1.1230x; 1.1230x over previous
#include <cuda_runtime.h>
#include <cuda_bf16.h>
#include <math.h>
#include <float.h>
#include <stdint.h>

// Problem constants
#define BB 16
#define NN 1000
#define EE 4000
#define DD 256
#define NH 4
#define HD 1024
#define LL 64
#define ACT 128
#define OO 256
#define G3 768
#define QKVS_W 4096

// ================= scratch (device globals) =================
__device__ __align__(16) __nv_bfloat16 g_xhi[BB*NN*DD],  g_xlo[BB*NN*DD];
__device__ __align__(16) __nv_bfloat16 g_eahi[BB*EE*DD], g_ealo[BB*EE*DD];
__device__ __align__(16) float g_qkvs[(size_t)BB*NN*QKVS_W];   // q|k|v|skip
__device__ __align__(16) float g_e[(size_t)BB*EE*HD];
__device__ __align__(16) __nv_bfloat16 g_hhi[(size_t)BB*NN*HD], g_hlo[(size_t)BB*NN*HD];
__device__ __align__(16) float g_gr[BB*NN*DD];
__device__ int   g_cnt[BB*NN];
__device__ int   g_off[BB*NN];
__device__ int   g_cur[BB*NN];
__device__ int   g_eord[BB*EE];
__device__ __align__(16) __nv_bfloat16 g_invehi[BB*LL*DD], g_invelo[BB*LL*DD];
__device__ __align__(16) __nv_bfloat16 g_invhhi[BB*LL*DD], g_invhlo[BB*LL*DD];
__device__ __align__(16) float g_gx[BB*LL*G3];
__device__ __align__(16) float g_W4[DD*G3];     // W_hh packed (j4, g, 4)
__device__ float g_invvec[BB*OO];
__device__ float g_biasN[QKVS_W];
// bf16 split weight buffers, [N,K] layout (k contiguous)
__device__ __align__(16) __nv_bfloat16 g_bhiN[QKVS_W*DD], g_bloN[QKVS_W*DD];
__device__ __align__(16) __nv_bfloat16 g_bhiE[HD*DD],  g_bloE[HD*DD];
__device__ __align__(16) __nv_bfloat16 g_bhi_w1[DD*HD], g_blo_w1[DD*HD];
__device__ __align__(16) __nv_bfloat16 g_bhi_wp[DD*DD], g_blo_wp[DD*DD];
__device__ __align__(16) __nv_bfloat16 g_bhi_ih[G3*DD], g_blo_ih[G3*DD];

// ================= helpers =================
__device__ __forceinline__ uint32_t smem_to_u32(const void* smem_ptr) {
    uint32_t addr;
    asm("{ .reg .u64 tmp; cvta.to.shared.u64 tmp, %1; cvt.u32.u64 %0, tmp; }"
        : "=r"(addr) : "l"(smem_ptr));
    return addr;
}
__device__ __forceinline__ void ldsm4(uint32_t r[4], uint32_t addr) {
    asm volatile("ldmatrix.sync.aligned.m8n8.x4.shared.b16 {%0,%1,%2,%3}, [%4];"
        : "=r"(r[0]), "=r"(r[1]), "=r"(r[2]), "=r"(r[3]) : "r"(addr));
}
__device__ __forceinline__ void mma16816(float c[4], uint32_t a0, uint32_t a1,
                                         uint32_t a2, uint32_t a3,
                                         uint32_t b0, uint32_t b1) {
    asm volatile(
        "mma.sync.aligned.m16n8k16.row.col.f32.bf16.bf16.f32 "
        "{%0,%1,%2,%3}, {%4,%5,%6,%7}, {%8,%9}, {%0,%1,%2,%3};"
        : "+f"(c[0]), "+f"(c[1]), "+f"(c[2]), "+f"(c[3])
        : "r"(a0), "r"(a1), "r"(a2), "r"(a3), "r"(b0), "r"(b1));
}
__device__ __forceinline__ void cpasync16(uint32_t dst, const void* src) {
    asm volatile("cp.async.cg.shared.global [%0], [%1], 16;" :: "r"(dst), "l"(src));
}
__device__ __forceinline__ void cp_commit() {
    asm volatile("cp.async.commit_group;");
}
template<int N> __device__ __forceinline__ void cp_wait() {
    asm volatile("cp.async.wait_group %0;" :: "n"(N));
}
__device__ __forceinline__ void split2(float a, float b, uint32_t& hw, uint32_t& lw) {
    __nv_bfloat162 hp = __floats2bfloat162_rn(a, b);
    float2 hf = __bfloat1622float2(hp);
    __nv_bfloat162 lp = __floats2bfloat162_rn(a - hf.x, b - hf.y);
    hw = *reinterpret_cast<uint32_t*>(&hp);
    lw = *reinterpret_cast<uint32_t*>(&lp);
}

// ================= gathers / conversions =================
// 128 threads, 2 elems each; packed bf16x2 writes
__global__ void gather_split_k(__nv_bfloat16* __restrict__ hi, __nv_bfloat16* __restrict__ lo,
                               const float* __restrict__ emb, const int* __restrict__ idx) {
    int row = blockIdx.x, t = threadIdx.x;
    int tok = idx[row];
    float2 f = *(const float2*)(emb + (size_t)tok*DD + 2*t);
    uint32_t hw, lw;
    split2(f.x, f.y, hw, lw);
    *(uint32_t*)(hi + (size_t)row*DD + 2*t) = hw;
    *(uint32_t*)(lo + (size_t)row*DD + 2*t) = lw;
}
// pack W_hh[768,256] -> W4[(j/4)*768 + g][4]
__global__ void packWhh_k(const float* __restrict__ Whh, float* __restrict__ W4) {
    int g = blockIdx.x, j4 = threadIdx.x;   // 768 blocks, 64 threads
    float4 v = *(const float4*)(Whh + (size_t)g*DD + 4*j4);
    *(float4*)(W4 + ((size_t)j4*G3 + g)*4) = v;
}
// W[K,N] fp32 -> Bhi/Blo [N,K] bf16
__global__ void convWT_k(const float* __restrict__ W, __nv_bfloat16* __restrict__ bhi,
                         __nv_bfloat16* __restrict__ blo, int K, int N) {
    int k = blockIdx.x;
    for (int n = threadIdx.x; n < N; n += blockDim.x) {
        float f = W[(size_t)k*N + n];
        __nv_bfloat16 h = __float2bfloat16_rn(f);
        bhi[(size_t)n*K + k] = h;
        blo[(size_t)n*K + k] = __float2bfloat16_rn(f - __bfloat162float(h));
    }
}
__global__ void convWN_k(const float* __restrict__ W, __nv_bfloat16* __restrict__ bhi,
                         __nv_bfloat16* __restrict__ blo, int total) {
    int i = blockIdx.x * blockDim.x + threadIdx.x;
    if (i >= total) return;
    float f = W[i];
    __nv_bfloat16 h = __float2bfloat16_rn(f);
    bhi[i] = h;
    blo[i] = __float2bfloat16_rn(f - __bfloat162float(h));
}
__global__ void biascat_k(const float* __restrict__ b0, const float* __restrict__ b1,
                          const float* __restrict__ b2, const float* __restrict__ b3,
                          float* __restrict__ o) {
    int t = blockIdx.x * 256 + threadIdx.x;
    const float* src = (t < 1024) ? b0 : (t < 2048) ? b1 : (t < 3072) ? b2 : b3;
    o[t] = src[t & 1023];
}

// ================= mma.sync bf16x3 GEMM (pre-split A and B) =================
#define KC 32
#define RSB 80
#define STG_A_HI 0
#define STG_A_LO 10240
#define STG_B_HI 20480
#define STG_B_LO 30720
#define STAGE_SZ 40960
#define NSTAGE 4
#define GEMM_SMEM (NSTAGE*STAGE_SZ)

template<int CRELU, int HASBIAS, int OUTSPLIT>
__global__ __launch_bounds__(256, 1) void mmagemm_k(
    const __nv_bfloat16* __restrict__ Ahi, const __nv_bfloat16* __restrict__ Alo,
    const __nv_bfloat16* __restrict__ Bhi, const __nv_bfloat16* __restrict__ Blo,
    const float* __restrict__ bias, float* __restrict__ C,
    __nv_bfloat16* __restrict__ Chi, __nv_bfloat16* __restrict__ Clo,
    int Nld, int K) {
    extern __shared__ char smc[];
    const uint32_t smb = smem_to_u32(smc);
    const int t = threadIdx.x, lane = t & 31, warp = t >> 5;
    const int bm = blockIdx.y * 128, bn = blockIdx.x * 128;
    const int wm = (warp >> 2) * 64, wn = (warp & 3) * 32;

    const int fr = t >> 1, fk = (t & 1) * 16;
    const __nv_bfloat16* Ah = Ahi + (size_t)(bm + fr) * K + fk;
    const __nv_bfloat16* Al = Alo + (size_t)(bm + fr) * K + fk;
    const __nv_bfloat16* Bh = Bhi + (size_t)(bn + fr) * K + fk;
    const __nv_bfloat16* Bl = Blo + (size_t)(bn + fr) * K + fk;
    const uint32_t fillOff = smb + (uint32_t)(fr * RSB + fk * 2);

    const uint32_t aBase = smb + (uint32_t)(wm + (lane & 15)) * RSB + (uint32_t)(lane >> 4) * 16;
    const uint32_t bBase = smb + (uint32_t)(wn + ((lane >> 4) << 3) + (lane & 7)) * RSB
                               + (uint32_t)((lane >> 3) & 1) * 16;

    float acc[4][4][4];
#pragma unroll
    for (int i = 0; i < 4; i++)
#pragma unroll
        for (int j = 0; j < 4; j++)
#pragma unroll
            for (int k = 0; k < 4; k++) acc[i][j][k] = 0.f;

    const int NC = K / KC;
#pragma unroll
    for (int c = 0; c < NSTAGE - 1; c++) {
        uint32_t d = fillOff + (uint32_t)(c * STAGE_SZ);
        const __nv_bfloat16* a0 = Ah + c * KC;
        const __nv_bfloat16* a1 = Al + c * KC;
        const __nv_bfloat16* b0 = Bh + c * KC;
        const __nv_bfloat16* b1 = Bl + c * KC;
        cpasync16(d + STG_A_HI,      a0);
        cpasync16(d + STG_A_HI + 16, a0 + 8);
        cpasync16(d + STG_A_LO,      a1);
        cpasync16(d + STG_A_LO + 16, a1 + 8);
        cpasync16(d + STG_B_HI,      b0);
        cpasync16(d + STG_B_HI + 16, b0 + 8);
        cpasync16(d + STG_B_LO,      b1);
        cpasync16(d + STG_B_LO + 16, b1 + 8);
        cp_commit();
    }

    for (int c = 0; c < NC; c++) {
        cp_wait<NSTAGE - 2>();
        __syncthreads();
        const uint32_t stg = (uint32_t)((c & (NSTAGE - 1)) * STAGE_SZ);
#pragma unroll
        for (int ks = 0; ks < 2; ks++) {
            const uint32_t kb = (uint32_t)(ks * 32);
#pragma unroll
            for (int pass = 0; pass < 3; pass++) {
                const uint32_t selA = (pass == 1) ? STG_A_LO : STG_A_HI;
                const uint32_t selB = (pass == 2) ? STG_B_LO : STG_B_HI;
                uint32_t ar[4][4];
#pragma unroll
                for (int mi = 0; mi < 4; mi++)
                    ldsm4(ar[mi], aBase + stg + selA + (uint32_t)(mi * 16 * RSB) + kb);
                uint32_t br[2][4];
#pragma unroll
                for (int nb = 0; nb < 2; nb++)
                    ldsm4(br[nb], bBase + stg + selB + (uint32_t)(nb * 16 * RSB) + kb);
#pragma unroll
                for (int mi = 0; mi < 4; mi++)
#pragma unroll
                    for (int ni = 0; ni < 4; ni++)
                        mma16816(acc[mi][ni], ar[mi][0], ar[mi][1], ar[mi][2], ar[mi][3],
                                 br[ni>>1][(ni&1)*2], br[ni>>1][(ni&1)*2+1]);
            }
        }
        __syncthreads();
        const int nx = c + NSTAGE - 1;
        if (nx < NC) {
            uint32_t d = fillOff + (uint32_t)((nx & (NSTAGE - 1)) * STAGE_SZ);
            const __nv_bfloat16* a0 = Ah + nx * KC;
            const __nv_bfloat16* a1 = Al + nx * KC;
            const __nv_bfloat16* b0 = Bh + nx * KC;
            const __nv_bfloat16* b1 = Bl + nx * KC;
            cpasync16(d + STG_A_HI,      a0);
            cpasync16(d + STG_A_HI + 16, a0 + 8);
            cpasync16(d + STG_A_LO,      a1);
            cpasync16(d + STG_A_LO + 16, a1 + 8);
            cpasync16(d + STG_B_HI,      b0);
            cpasync16(d + STG_B_HI + 16, b0 + 8);
            cpasync16(d + STG_B_LO,      b1);
            cpasync16(d + STG_B_LO + 16, b1 + 8);
        }
        cp_commit();
    }

#pragma unroll
    for (int mi = 0; mi < 4; mi++) {
        const int r0 = bm + wm + mi*16 + (lane >> 2);
#pragma unroll
        for (int ni = 0; ni < 4; ni++) {
            const int col = bn + wn + ni*8 + (lane & 3)*2;
            float bx = 0.f, by = 0.f;
            if (HASBIAS) { bx = bias[col]; by = bias[col+1]; }
            float v0 = acc[mi][ni][0] + bx, v1 = acc[mi][ni][1] + by;
            float v2 = acc[mi][ni][2] + bx, v3 = acc[mi][ni][3] + by;
            if (CRELU) {
                v0 = fmaxf(v0, 0.f); v1 = fmaxf(v1, 0.f);
                v2 = fmaxf(v2, 0.f); v3 = fmaxf(v3, 0.f);
            }
            if (OUTSPLIT) {
                uint32_t hw0, lw0, hw1, lw1;
                split2(v0, v1, hw0, lw0);
                split2(v2, v3, hw1, lw1);
                *(uint32_t*)(Chi + (size_t)r0 * Nld + col) = hw0;
                *(uint32_t*)(Clo + (size_t)r0 * Nld + col) = lw0;
                *(uint32_t*)(Chi + (size_t)(r0+8) * Nld + col) = hw1;
                *(uint32_t*)(Clo + (size_t)(r0+8) * Nld + col) = lw1;
            } else {
                *(float2*)(C + (size_t)r0 * Nld + col) = make_float2(v0, v1);
                *(float2*)(C + (size_t)(r0+8) * Nld + col) = make_float2(v2, v3);
            }
        }
    }
}

// ================= CSR build over dst =================
__global__ void zero_cnt_k() {
    int i = blockIdx.x * blockDim.x + threadIdx.x;
    if (i < BB*NN) g_cnt[i] = 0;
}
__global__ void count_k(const int* __restrict__ ei) {
    int i = blockIdx.x * blockDim.x + threadIdx.x;
    if (i >= BB*EE) return;
    int b = i / EE, e = i % EE;
    int dst = ei[(b*2 + 1)*EE + e];
    atomicAdd(&g_cnt[b*NN + dst], 1);
}
__global__ void scan_k() {
    int b = blockIdx.x;
    if (threadIdx.x == 0) {
        int run = 0;
        for (int n = 0; n < NN; n++) {
            g_off[b*NN + n] = run;
            g_cur[b*NN + n] = run;
            run += g_cnt[b*NN + n];
        }
    }
}
__global__ void fill_k(const int* __restrict__ ei) {
    int i = blockIdx.x * blockDim.x + threadIdx.x;
    if (i >= BB*EE) return;
    int b = i / EE, e = i % EE;
    int dst = ei[(b*2 + 1)*EE + e];
    int pos = atomicAdd(&g_cur[b*NN + dst], 1);
    g_eord[b*EE + pos] = e;
}

// ================= fused attention (online softmax) =================
// warp per (b,node,head): single pass over incident edges; e row read once.
// epilogue: h = relu(skip + agg) -> split bf16 hi/lo.
__global__ void attn_fused_k(const int* __restrict__ ei) {
    int g = blockIdx.x * 4 + (threadIdx.x >> 5);
    int lane = threadIdx.x & 31;
    if (g >= BB*NN*NH) return;
    int h = g & 3, bn = g >> 2;
    int b = bn / NN;
    int deg = g_cnt[bn], off = g_off[bn];

    const float* qp = g_qkvs + (size_t)bn*QKVS_W + h*DD;
    float2 qr[4];
#pragma unroll
    for (int r = 0; r < 4; r++) qr[r] = *(const float2*)(qp + 2*lane + 64*r);

    float m = -3.0e38f, den = 0.f;
    float2 o[4];
#pragma unroll
    for (int r = 0; r < 4; r++) o[r] = make_float2(0.f, 0.f);

    for (int i = 0; i < deg; i++) {
        int e = g_eord[b*EE + off + i];
        int src = ei[(b*2)*EE + e];
        const float* base = g_qkvs + (size_t)(b*NN + src)*QKVS_W;
        const float* kp = base + HD + h*DD;
        const float* vp = base + 2*HD + h*DD;
        const float* ep = g_e + (size_t)(b*EE + e)*HD + h*DD;
        float2 ev[4], vv[4];
        float a = 0.f;
#pragma unroll
        for (int r = 0; r < 4; r++) {
            int d = 2*lane + 64*r;
            ev[r] = *(const float2*)(ep + d);
            float2 kv = *(const float2*)(kp + d);
            vv[r] = *(const float2*)(vp + d);
            a += qr[r].x * (kv.x + ev[r].x) + qr[r].y * (kv.y + ev[r].y);
        }
#pragma unroll
        for (int dlt = 16; dlt; dlt >>= 1) a += __shfl_xor_sync(0xffffffffu, a, dlt);
        a *= 0.0625f;
        float mn = fmaxf(m, a);
        float scale = expf(m - mn);
        float w = expf(a - mn);
        den = den * scale + w;
#pragma unroll
        for (int r = 0; r < 4; r++) {
            o[r].x = o[r].x * scale + w * (vv[r].x + ev[r].x);
            o[r].y = o[r].y * scale + w * (vv[r].y + ev[r].y);
        }
        m = mn;
    }
    float invden = (deg > 0) ? (1.f / den) : 0.f;
    const float* sp = g_qkvs + (size_t)bn*QKVS_W + 3*HD + h*DD;
    __nv_bfloat16* hhi = g_hhi + (size_t)bn*HD + h*DD;
    __nv_bfloat16* hlo = g_hlo + (size_t)bn*HD + h*DD;
#pragma unroll
    for (int r = 0; r < 4; r++) {
        int d = 2*lane + 64*r;
        float2 sk = *(const float2*)(sp + d);
        float f0 = fmaxf(sk.x + o[r].x * invden, 0.f);
        float f1 = fmaxf(sk.y + o[r].y * invden, 0.f);
        uint32_t hw, lw;
        split2(f0, f1, hw, lw);
        *(uint32_t*)(hhi + d) = hw;
        *(uint32_t*)(hlo + d) = lw;
    }
}

// ================= inv path =================
__global__ void mixed_inv_split_k(const int* __restrict__ tok, const int* __restrict__ nod,
                                  const float* __restrict__ emb) {
    int row = blockIdx.x, t = threadIdx.x;   // 128 threads
    int b = row / LL;
    int tk = tok[row], nd = nod[row];
    float2 f0 = *(const float2*)(emb + (size_t)tk*DD + 2*t);
    float2 f1 = *(const float2*)(g_gr + (size_t)(b*NN + nd)*DD + 2*t);
    uint32_t hw, lw;
    split2(f0.x + f1.x, f0.y + f1.y, hw, lw);
    *(uint32_t*)(g_invehi + (size_t)row*DD + 2*t) = hw;
    *(uint32_t*)(g_invelo + (size_t)row*DD + 2*t) = lw;
}

// GRU: one block per batch, 768 threads, W packed float4 over k
__global__ void gru_k(const float* __restrict__ b_hh) {
    __shared__ float hs[256];
    __shared__ float ghs[768];
    int b = blockIdx.x, t = threadIdx.x;
    if (t < 256) hs[t] = 0.f;
    float bh = b_hh[t];
    const float4* W4 = (const float4*)g_W4;
    __syncthreads();
    for (int l = 0; l < LL; l++) {
        float acc = bh;
#pragma unroll 8
        for (int j4 = 0; j4 < 64; j4++) {
            float4 wv = W4[j4 * G3 + t];
            float4 hv = *(const float4*)(hs + 4*j4);
            acc += hv.x*wv.x + hv.y*wv.y + hv.z*wv.z + hv.w*wv.w;
        }
        ghs[t] = acc;
        __syncthreads();
        float hn = 0.f;
        if (t < 256) {
            const float* g = g_gx + (size_t)(b*LL + l)*G3;
            float r = 1.f / (1.f + expf(-(g[t]       + ghs[t])));
            float z = 1.f / (1.f + expf(-(g[256 + t] + ghs[256 + t])));
            float c = tanhf(g[512 + t] + r * ghs[512 + t]);
            hn = (1.f - z) * c + z * hs[t];
        }
        __syncthreads();
        if (t < 256) hs[t] = hn;
        __syncthreads();
    }
    if (t < 256) g_invvec[b*OO + t] = hs[t];
}

// ================= scoring =================
__global__ void score_k(const float* __restrict__ Wap, const float* __restrict__ bap,
                        const float* __restrict__ Wab, const float* __restrict__ bab,
                        const int* __restrict__ aa_token, const int* __restrict__ aa_node,
                        const float* __restrict__ mask, const float* __restrict__ emb,
                        float* __restrict__ out) {
    __shared__ float invs[256];
    __shared__ float u[256];
    __shared__ float red[256];
    int b = blockIdx.x, t = threadIdx.x;
    int warp = t >> 5, lane = t & 31;
    invs[t] = g_invvec[b*OO + t];
    __syncthreads();
    for (int d = warp*32; d < warp*32 + 32; d++) {
        float acc = 0.f;
#pragma unroll
        for (int r = 0; r < 8; r++) {
            int o = lane + 32*r;
            acc += Wap[(size_t)d*OO + o] * invs[o];
        }
#pragma unroll
        for (int dd = 16; dd; dd >>= 1) acc += __shfl_xor_sync(0xffffffffu, acc, dd);
        if (lane == 0) u[d] = acc + Wab[d];
    }
    red[t] = bap[t] * invs[t];
    __syncthreads();
    for (int s = 128; s; s >>= 1) {
        if (t < s) red[t] += red[t + s];
        __syncthreads();
    }
    float cb = red[0] + bab[0];
    for (int a = warp; a < ACT; a += 8) {
        int tok = aa_token[b*ACT + a], nod = aa_node[b*ACT + a];
        const float* er = emb + (size_t)tok*DD;
        const float* gg = g_gr + (size_t)(b*NN + nod)*DD;
        float acc = 0.f;
#pragma unroll
        for (int r = 0; r < 8; r++) {
            int d = lane + 32*r;
            acc += (er[d] + gg[d]) * u[d];
        }
#pragma unroll
        for (int dd = 16; dd; dd >>= 1) acc += __shfl_xor_sync(0xffffffffu, acc, dd);
        if (lane == 0) {
            float mk = mask[b*ACT + a];
            float lm = fmaxf(logf(mk), -FLT_MAX);
            out[b*ACT + a] = acc + cb + lm;
        }
    }
}

// ================= host launcher =================
extern "C" void kernel_launch(void* const* d_in, const int* in_sizes, int n_in,
                              void* d_out, int out_size) {
    const int*   node_tokens = (const int*)d_in[0];
    const int*   edge_tokens = (const int*)d_in[1];
    const int*   edge_index  = (const int*)d_in[2];
    const int*   inv_token   = (const int*)d_in[3];
    const int*   inv_node    = (const int*)d_in[4];
    const int*   aa_token    = (const int*)d_in[5];
    const int*   aa_node     = (const int*)d_in[6];
    const float* action_mask = (const float*)d_in[7];
    const float* emb         = (const float*)d_in[8];
    const float* Wq  = (const float*)d_in[9];
    const float* bq  = (const float*)d_in[10];
    const float* Wk  = (const float*)d_in[11];
    const float* bk  = (const float*)d_in[12];
    const float* Wv  = (const float*)d_in[13];
    const float* bv  = (const float*)d_in[14];
    const float* We  = (const float*)d_in[15];
    const float* Wsk = (const float*)d_in[16];
    const float* bsk = (const float*)d_in[17];
    const float* W1  = (const float*)d_in[18];
    const float* b1  = (const float*)d_in[19];
    const float* Wp  = (const float*)d_in[20];
    const float* bp  = (const float*)d_in[21];
    const float* W_ih = (const float*)d_in[22];
    const float* W_hh = (const float*)d_in[23];
    const float* b_ih = (const float*)d_in[24];
    const float* b_hh = (const float*)d_in[25];
    const float* Wab = (const float*)d_in[26];
    const float* bab = (const float*)d_in[27];
    const float* Wap = (const float*)d_in[28];
    const float* bap = (const float*)d_in[29];
    float* out = (float*)d_out;

    void* p;
    __nv_bfloat16 *xhi, *xlo, *eahi, *ealo, *hhi, *hlo, *invehi, *invelo, *invhhi, *invhlo;
    __nv_bfloat16 *bhiN, *bloN, *bhiE, *bloE, *bh1, *bl1, *bhp, *blp, *bhih, *blih;
    float *qkvs, *e_, *gr_, *gx_, *W4_, *biasN;
    cudaGetSymbolAddress(&p, g_xhi);    xhi = (__nv_bfloat16*)p;
    cudaGetSymbolAddress(&p, g_xlo);    xlo = (__nv_bfloat16*)p;
    cudaGetSymbolAddress(&p, g_eahi);   eahi = (__nv_bfloat16*)p;
    cudaGetSymbolAddress(&p, g_ealo);   ealo = (__nv_bfloat16*)p;
    cudaGetSymbolAddress(&p, g_qkvs);   qkvs = (float*)p;
    cudaGetSymbolAddress(&p, g_e);      e_ = (float*)p;
    cudaGetSymbolAddress(&p, g_hhi);    hhi = (__nv_bfloat16*)p;
    cudaGetSymbolAddress(&p, g_hlo);    hlo = (__nv_bfloat16*)p;
    cudaGetSymbolAddress(&p, g_gr);     gr_ = (float*)p;
    cudaGetSymbolAddress(&p, g_invehi); invehi = (__nv_bfloat16*)p;
    cudaGetSymbolAddress(&p, g_invelo); invelo = (__nv_bfloat16*)p;
    cudaGetSymbolAddress(&p, g_invhhi); invhhi = (__nv_bfloat16*)p;
    cudaGetSymbolAddress(&p, g_invhlo); invhlo = (__nv_bfloat16*)p;
    cudaGetSymbolAddress(&p, g_gx);     gx_ = (float*)p;
    cudaGetSymbolAddress(&p, g_W4);     W4_ = (float*)p;
    cudaGetSymbolAddress(&p, g_biasN);  biasN = (float*)p;
    cudaGetSymbolAddress(&p, g_bhiN);   bhiN = (__nv_bfloat16*)p;
    cudaGetSymbolAddress(&p, g_bloN);   bloN = (__nv_bfloat16*)p;
    cudaGetSymbolAddress(&p, g_bhiE);   bhiE = (__nv_bfloat16*)p;
    cudaGetSymbolAddress(&p, g_bloE);   bloE = (__nv_bfloat16*)p;
    cudaGetSymbolAddress(&p, g_bhi_w1); bh1 = (__nv_bfloat16*)p;
    cudaGetSymbolAddress(&p, g_blo_w1); bl1 = (__nv_bfloat16*)p;
    cudaGetSymbolAddress(&p, g_bhi_wp); bhp = (__nv_bfloat16*)p;
    cudaGetSymbolAddress(&p, g_blo_wp); blp = (__nv_bfloat16*)p;
    cudaGetSymbolAddress(&p, g_bhi_ih); bhih = (__nv_bfloat16*)p;
    cudaGetSymbolAddress(&p, g_blo_ih); blih = (__nv_bfloat16*)p;

    cudaFuncSetAttribute(mmagemm_k<0,1,0>, cudaFuncAttributeMaxDynamicSharedMemorySize, GEMM_SMEM);
    cudaFuncSetAttribute(mmagemm_k<0,0,0>, cudaFuncAttributeMaxDynamicSharedMemorySize, GEMM_SMEM);
    cudaFuncSetAttribute(mmagemm_k<1,1,0>, cudaFuncAttributeMaxDynamicSharedMemorySize, GEMM_SMEM);
    cudaFuncSetAttribute(mmagemm_k<1,1,1>, cudaFuncAttributeMaxDynamicSharedMemorySize, GEMM_SMEM);

    // Launch order arranged so the EDGE GEMM is launch index 5 (ncu -s 5 -c 1).
    gather_split_k<<<BB*NN, 128>>>(xhi, xlo, emb, node_tokens);           // 0
    gather_split_k<<<BB*EE, 128>>>(eahi, ealo, emb, edge_tokens);         // 1
    convWT_k<<<DD, 256>>>(We, bhiE, bloE, DD, HD);                        // 2
    packWhh_k<<<G3, 64>>>(W_hh, W4_);                                     // 3
    convWN_k<<<(G3*DD + 255)/256, 256>>>(W_ih, bhih, blih, G3*DD);        // 4

    // 5: edge projection GEMM [64000,256] @ [256,1024]  <-- PROFILED
    dim3 gedge(HD/128, (BB*EE)/128);
    mmagemm_k<0,0,0><<<gedge, 256, GEMM_SMEM>>>(eahi, ealo, bhiE, bloE, nullptr,
                                                e_, nullptr, nullptr, HD, DD);

    convWT_k<<<DD, 256>>>(Wq,  bhiN,           bloN,           DD, HD);   // 6
    convWT_k<<<DD, 256>>>(Wk,  bhiN + 1024*DD, bloN + 1024*DD, DD, HD);   // 7
    convWT_k<<<DD, 256>>>(Wv,  bhiN + 2048*DD, bloN + 2048*DD, DD, HD);   // 8
    convWT_k<<<DD, 256>>>(Wsk, bhiN + 3072*DD, bloN + 3072*DD, DD, HD);   // 9
    biascat_k<<<16, 256>>>(bq, bk, bv, bsk, biasN);                       // 10

    // combined node projections: [16000,256] @ [256,4096]
    dim3 gproj(QKVS_W/128, (BB*NN)/128);
    mmagemm_k<0,1,0><<<gproj, 256, GEMM_SMEM>>>(xhi, xlo, bhiN, bloN, biasN,
                                                qkvs, nullptr, nullptr, QKVS_W, DD);

    // CSR over dst
    zero_cnt_k<<<(BB*NN + 255)/256, 256>>>();
    count_k<<<(BB*EE + 255)/256, 256>>>(edge_index);
    scan_k<<<BB, 32>>>();
    fill_k<<<(BB*EE + 255)/256, 256>>>(edge_index);

    // fused attention + skip + relu + split
    attn_fused_k<<<(BB*NN*NH + 3)/4, 128>>>(edge_index);

    // graph_repr = relu(h@W1 + b1)
    convWT_k<<<HD, 256>>>(W1, bh1, bl1, HD, DD);
    dim3 ggr(DD/128, (BB*NN)/128);
    mmagemm_k<1,1,0><<<ggr, 256, GEMM_SMEM>>>(hhi, hlo, bh1, bl1, b1,
                                              gr_, nullptr, nullptr, DD, HD);

    // inv path
    mixed_inv_split_k<<<BB*LL, 128>>>(inv_token, inv_node, emb);
    convWT_k<<<DD, 256>>>(Wp, bhp, blp, DD, DD);
    dim3 ginv(DD/128, (BB*LL)/128);
    mmagemm_k<1,1,1><<<ginv, 256, GEMM_SMEM>>>(invehi, invelo, bhp, blp, bp,
                                               nullptr, invhhi, invhlo, DD, DD);
    dim3 ggx(G3/128, (BB*LL)/128);
    mmagemm_k<0,1,0><<<ggx, 256, GEMM_SMEM>>>(invhhi, invhlo, bhih, blih, b_ih,
                                              gx_, nullptr, nullptr, G3, DD);
    gru_k<<<BB, 768>>>(b_hh);

    // scores
    score_k<<<BB, 256>>>(Wap, bap, Wab, bab, aa_token, aa_node, action_mask, emb, out);
    (void)in_sizes; (void)n_in; (void)out_size;
}

// round 9
// speedup vs baseline: 1.3317x; 1.1858x over previous
#include <cuda_runtime.h>
#include <cuda_fp16.h>
#include <math.h>
#include <float.h>
#include <stdint.h>

// Problem constants
#define BB 16
#define NN 1000
#define EE 4000
#define DD 256
#define NH 4
#define HD 1024
#define LL 64
#define ACT 128
#define OO 256
#define G3 768
#define QKVS_W 4096

// ================= scratch (device globals) =================
__device__ __align__(16) __half g_xhi[BB*NN*DD],  g_xlo[BB*NN*DD];
__device__ __align__(16) __half g_eahi[BB*EE*DD], g_ealo[BB*EE*DD];
__device__ __align__(16) float g_qkvs[(size_t)BB*NN*QKVS_W];   // q|k|v|skip
__device__ __align__(16) __half g_e[(size_t)BB*EE*HD];         // fp16 edge proj
__device__ __align__(16) __half g_hhi[(size_t)BB*NN*HD], g_hlo[(size_t)BB*NN*HD];
__device__ __align__(16) float g_gr[BB*NN*DD];
__device__ int   g_cnt[BB*NN];
__device__ int   g_off[BB*NN];
__device__ int   g_cur[BB*NN];
__device__ int   g_eord[BB*EE];
__device__ __align__(16) __half g_invehi[BB*LL*DD], g_invelo[BB*LL*DD];
__device__ __align__(16) __half g_invhhi[BB*LL*DD], g_invhlo[BB*LL*DD];
__device__ __align__(16) float g_gx[BB*LL*G3];
__device__ __align__(16) __half g_Wh8[DD*G3];   // W_hh fp16 packed (j8, g, 8)
__device__ float g_invvec[BB*OO];
__device__ float g_biasN[QKVS_W];
// fp16 weight buffers, [N,K] layout (k contiguous), single precision copy
__device__ __align__(16) __half g_bN[QKVS_W*DD];
__device__ __align__(16) __half g_bE[HD*DD];
__device__ __align__(16) __half g_bw1[DD*HD];
__device__ __align__(16) __half g_bwp[DD*DD];
__device__ __align__(16) __half g_bih[G3*DD];

// ================= helpers =================
__device__ __forceinline__ uint32_t smem_to_u32(const void* smem_ptr) {
    uint32_t addr;
    asm("{ .reg .u64 tmp; cvta.to.shared.u64 tmp, %1; cvt.u32.u64 %0, tmp; }"
        : "=r"(addr) : "l"(smem_ptr));
    return addr;
}
__device__ __forceinline__ void ldsm4(uint32_t r[4], uint32_t addr) {
    asm volatile("ldmatrix.sync.aligned.m8n8.x4.shared.b16 {%0,%1,%2,%3}, [%4];"
        : "=r"(r[0]), "=r"(r[1]), "=r"(r[2]), "=r"(r[3]) : "r"(addr));
}
__device__ __forceinline__ void mma16816h(float c[4], uint32_t a0, uint32_t a1,
                                          uint32_t a2, uint32_t a3,
                                          uint32_t b0, uint32_t b1) {
    asm volatile(
        "mma.sync.aligned.m16n8k16.row.col.f32.f16.f16.f32 "
        "{%0,%1,%2,%3}, {%4,%5,%6,%7}, {%8,%9}, {%0,%1,%2,%3};"
        : "+f"(c[0]), "+f"(c[1]), "+f"(c[2]), "+f"(c[3])
        : "r"(a0), "r"(a1), "r"(a2), "r"(a3), "r"(b0), "r"(b1));
}
__device__ __forceinline__ void cpasync16(uint32_t dst, const void* src) {
    asm volatile("cp.async.cg.shared.global [%0], [%1], 16;" :: "r"(dst), "l"(src));
}
__device__ __forceinline__ void cp_commit() {
    asm volatile("cp.async.commit_group;");
}
template<int N> __device__ __forceinline__ void cp_wait() {
    asm volatile("cp.async.wait_group %0;" :: "n"(N));
}
// fp32 pair -> fp16 hi + fp16 lo (residual)
__device__ __forceinline__ void split2h(float a, float b, uint32_t& hw, uint32_t& lw) {
    __half2 hp = __floats2half2_rn(a, b);
    float2 hf = __half22float2(hp);
    __half2 lp = __floats2half2_rn(a - hf.x, b - hf.y);
    hw = *reinterpret_cast<uint32_t*>(&hp);
    lw = *reinterpret_cast<uint32_t*>(&lp);
}

// ================= gathers / conversions =================
__global__ void gather_split_k(__half* __restrict__ hi, __half* __restrict__ lo,
                               const float* __restrict__ emb, const int* __restrict__ idx) {
    int row = blockIdx.x, t = threadIdx.x;   // 128 threads
    int tok = idx[row];
    float2 f = *(const float2*)(emb + (size_t)tok*DD + 2*t);
    uint32_t hw, lw;
    split2h(f.x, f.y, hw, lw);
    *(uint32_t*)(hi + (size_t)row*DD + 2*t) = hw;
    *(uint32_t*)(lo + (size_t)row*DD + 2*t) = lw;
}
// pack W_hh[768,256] fp32 -> fp16 W8[(j/8)*768 + g][8]
__global__ void packWhh_h_k(const float* __restrict__ Whh, __half* __restrict__ W8) {
    int g = blockIdx.x, j8 = threadIdx.x;   // 768 blocks, 32 threads
    float4 a = *(const float4*)(Whh + (size_t)g*DD + 8*j8);
    float4 b = *(const float4*)(Whh + (size_t)g*DD + 8*j8 + 4);
    __half2 h0 = __floats2half2_rn(a.x, a.y);
    __half2 h1 = __floats2half2_rn(a.z, a.w);
    __half2 h2 = __floats2half2_rn(b.x, b.y);
    __half2 h3 = __floats2half2_rn(b.z, b.w);
    uint4 o;
    o.x = *reinterpret_cast<uint32_t*>(&h0);
    o.y = *reinterpret_cast<uint32_t*>(&h1);
    o.z = *reinterpret_cast<uint32_t*>(&h2);
    o.w = *reinterpret_cast<uint32_t*>(&h3);
    *(uint4*)(W8 + ((size_t)j8*G3 + g)*8) = o;
}
// W[K,N] fp32 -> B[N,K] fp16 (single)
__global__ void convWTh_k(const float* __restrict__ W, __half* __restrict__ bh,
                          int K, int N) {
    int k = blockIdx.x;
    for (int n = threadIdx.x; n < N; n += blockDim.x)
        bh[(size_t)n*K + k] = __float2half_rn(W[(size_t)k*N + n]);
}
__global__ void convWNh_k(const float* __restrict__ W, __half* __restrict__ bh, int total) {
    int i = blockIdx.x * blockDim.x + threadIdx.x;
    if (i < total) bh[i] = __float2half_rn(W[i]);
}
__global__ void biascat_k(const float* __restrict__ b0, const float* __restrict__ b1,
                          const float* __restrict__ b2, const float* __restrict__ b3,
                          float* __restrict__ o) {
    int t = blockIdx.x * 256 + threadIdx.x;
    const float* src = (t < 1024) ? b0 : (t < 2048) ? b1 : (t < 3072) ? b2 : b3;
    o[t] = src[t & 1023];
}

// ================= mma.sync fp16x2 GEMM =================
// C[M,N] = act(A@B^T + bias); A = Ahi+Alo fp16 [M,K]; B fp16 [N,K] (single).
// CTA 128x128, 8 warps, warp tile 64x32, K chunk 32, 4-stage cp.async pipeline.
// OUTMODE: 0 = fp32 C, 1 = fp16 C (Ch), 2 = fp16 hi/lo split (Chi/Clo).
#define KC 32
#define RSB 80
#define STG_A_HI 0
#define STG_A_LO 10240
#define STG_B    20480
#define STAGE_SZ 30720
#define NSTAGE 4
#define GEMM_SMEM (NSTAGE*STAGE_SZ)

template<int CRELU, int HASBIAS, int OUTMODE>
__global__ __launch_bounds__(256, 1) void mmagemm_k(
    const __half* __restrict__ Ahi, const __half* __restrict__ Alo,
    const __half* __restrict__ Bw, const float* __restrict__ bias,
    float* __restrict__ C, __half* __restrict__ Ch,
    __half* __restrict__ Chi, __half* __restrict__ Clo,
    int Nld, int K) {
    extern __shared__ char smc[];
    const uint32_t smb = smem_to_u32(smc);
    const int t = threadIdx.x, lane = t & 31, warp = t >> 5;
    const int bm = blockIdx.y * 128, bn = blockIdx.x * 128;
    const int wm = (warp >> 2) * 64, wn = (warp & 3) * 32;

    const int fr = t >> 1, fk = (t & 1) * 16;
    const __half* Ah = Ahi + (size_t)(bm + fr) * K + fk;
    const __half* Al = Alo + (size_t)(bm + fr) * K + fk;
    const __half* Bp = Bw  + (size_t)(bn + fr) * K + fk;
    const uint32_t fillOff = smb + (uint32_t)(fr * RSB + fk * 2);

    const uint32_t aBase = smb + (uint32_t)(wm + (lane & 15)) * RSB + (uint32_t)(lane >> 4) * 16;
    const uint32_t bBase = smb + (uint32_t)(wn + ((lane >> 4) << 3) + (lane & 7)) * RSB
                               + (uint32_t)((lane >> 3) & 1) * 16;

    float acc[4][4][4];
#pragma unroll
    for (int i = 0; i < 4; i++)
#pragma unroll
        for (int j = 0; j < 4; j++)
#pragma unroll
            for (int k = 0; k < 4; k++) acc[i][j][k] = 0.f;

    const int NC = K / KC;
#pragma unroll
    for (int c = 0; c < NSTAGE - 1; c++) {
        uint32_t d = fillOff + (uint32_t)(c * STAGE_SZ);
        const __half* a0 = Ah + c * KC;
        const __half* a1 = Al + c * KC;
        const __half* b0 = Bp + c * KC;
        cpasync16(d + STG_A_HI,      a0);
        cpasync16(d + STG_A_HI + 16, a0 + 8);
        cpasync16(d + STG_A_LO,      a1);
        cpasync16(d + STG_A_LO + 16, a1 + 8);
        cpasync16(d + STG_B,         b0);
        cpasync16(d + STG_B + 16,    b0 + 8);
        cp_commit();
    }

    for (int c = 0; c < NC; c++) {
        cp_wait<NSTAGE - 2>();
        __syncthreads();
        const uint32_t stg = (uint32_t)((c & (NSTAGE - 1)) * STAGE_SZ);
#pragma unroll
        for (int ks = 0; ks < 2; ks++) {
            const uint32_t kb = (uint32_t)(ks * 32);
            uint32_t br[2][4];
#pragma unroll
            for (int nb = 0; nb < 2; nb++)
                ldsm4(br[nb], bBase + stg + STG_B + (uint32_t)(nb * 16 * RSB) + kb);
#pragma unroll
            for (int pass = 0; pass < 2; pass++) {
                const uint32_t selA = pass ? STG_A_LO : STG_A_HI;
                uint32_t ar[4][4];
#pragma unroll
                for (int mi = 0; mi < 4; mi++)
                    ldsm4(ar[mi], aBase + stg + selA + (uint32_t)(mi * 16 * RSB) + kb);
#pragma unroll
                for (int mi = 0; mi < 4; mi++)
#pragma unroll
                    for (int ni = 0; ni < 4; ni++)
                        mma16816h(acc[mi][ni], ar[mi][0], ar[mi][1], ar[mi][2], ar[mi][3],
                                  br[ni>>1][(ni&1)*2], br[ni>>1][(ni&1)*2+1]);
            }
        }
        __syncthreads();
        const int nx = c + NSTAGE - 1;
        if (nx < NC) {
            uint32_t d = fillOff + (uint32_t)((nx & (NSTAGE - 1)) * STAGE_SZ);
            const __half* a0 = Ah + nx * KC;
            const __half* a1 = Al + nx * KC;
            const __half* b0 = Bp + nx * KC;
            cpasync16(d + STG_A_HI,      a0);
            cpasync16(d + STG_A_HI + 16, a0 + 8);
            cpasync16(d + STG_A_LO,      a1);
            cpasync16(d + STG_A_LO + 16, a1 + 8);
            cpasync16(d + STG_B,         b0);
            cpasync16(d + STG_B + 16,    b0 + 8);
        }
        cp_commit();
    }

#pragma unroll
    for (int mi = 0; mi < 4; mi++) {
        const int r0 = bm + wm + mi*16 + (lane >> 2);
#pragma unroll
        for (int ni = 0; ni < 4; ni++) {
            const int col = bn + wn + ni*8 + (lane & 3)*2;
            float bx = 0.f, by = 0.f;
            if (HASBIAS) { bx = bias[col]; by = bias[col+1]; }
            float v0 = acc[mi][ni][0] + bx, v1 = acc[mi][ni][1] + by;
            float v2 = acc[mi][ni][2] + bx, v3 = acc[mi][ni][3] + by;
            if (CRELU) {
                v0 = fmaxf(v0, 0.f); v1 = fmaxf(v1, 0.f);
                v2 = fmaxf(v2, 0.f); v3 = fmaxf(v3, 0.f);
            }
            if (OUTMODE == 0) {
                *(float2*)(C + (size_t)r0 * Nld + col) = make_float2(v0, v1);
                *(float2*)(C + (size_t)(r0+8) * Nld + col) = make_float2(v2, v3);
            } else if (OUTMODE == 1) {
                __half2 p0 = __floats2half2_rn(v0, v1);
                __half2 p1 = __floats2half2_rn(v2, v3);
                *(uint32_t*)(Ch + (size_t)r0 * Nld + col) = *reinterpret_cast<uint32_t*>(&p0);
                *(uint32_t*)(Ch + (size_t)(r0+8) * Nld + col) = *reinterpret_cast<uint32_t*>(&p1);
            } else {
                uint32_t hw0, lw0, hw1, lw1;
                split2h(v0, v1, hw0, lw0);
                split2h(v2, v3, hw1, lw1);
                *(uint32_t*)(Chi + (size_t)r0 * Nld + col) = hw0;
                *(uint32_t*)(Clo + (size_t)r0 * Nld + col) = lw0;
                *(uint32_t*)(Chi + (size_t)(r0+8) * Nld + col) = hw1;
                *(uint32_t*)(Clo + (size_t)(r0+8) * Nld + col) = lw1;
            }
        }
    }
}

// ================= CSR build over dst =================
__global__ void zero_cnt_k() {
    int i = blockIdx.x * blockDim.x + threadIdx.x;
    if (i < BB*NN) g_cnt[i] = 0;
}
__global__ void count_k(const int* __restrict__ ei) {
    int i = blockIdx.x * blockDim.x + threadIdx.x;
    if (i >= BB*EE) return;
    int b = i / EE, e = i % EE;
    int dst = ei[(b*2 + 1)*EE + e];
    atomicAdd(&g_cnt[b*NN + dst], 1);
}
__global__ void scan_k() {
    int b = blockIdx.x;
    if (threadIdx.x == 0) {
        int run = 0;
        for (int n = 0; n < NN; n++) {
            g_off[b*NN + n] = run;
            g_cur[b*NN + n] = run;
            run += g_cnt[b*NN + n];
        }
    }
}
__global__ void fill_k(const int* __restrict__ ei) {
    int i = blockIdx.x * blockDim.x + threadIdx.x;
    if (i >= BB*EE) return;
    int b = i / EE, e = i % EE;
    int dst = ei[(b*2 + 1)*EE + e];
    int pos = atomicAdd(&g_cur[b*NN + dst], 1);
    g_eord[b*EE + pos] = e;
}

// ================= fused attention (online softmax), e in fp16 =================
__global__ void attn_fused_k(const int* __restrict__ ei) {
    int g = blockIdx.x * 4 + (threadIdx.x >> 5);
    int lane = threadIdx.x & 31;
    if (g >= BB*NN*NH) return;
    int h = g & 3, bn = g >> 2;
    int b = bn / NN;
    int deg = g_cnt[bn], off = g_off[bn];

    const float* qp = g_qkvs + (size_t)bn*QKVS_W + h*DD;
    float2 qr[4];
#pragma unroll
    for (int r = 0; r < 4; r++) qr[r] = *(const float2*)(qp + 2*lane + 64*r);

    float m = -3.0e38f, den = 0.f;
    float2 o[4];
#pragma unroll
    for (int r = 0; r < 4; r++) o[r] = make_float2(0.f, 0.f);

    for (int i = 0; i < deg; i++) {
        int e = g_eord[b*EE + off + i];
        int src = ei[(b*2)*EE + e];
        const float* base = g_qkvs + (size_t)(b*NN + src)*QKVS_W;
        const float* kp = base + HD + h*DD;
        const float* vp = base + 2*HD + h*DD;
        const __half* ep = g_e + (size_t)(b*EE + e)*HD + h*DD;
        float2 ev[4], vv[4];
        float a = 0.f;
#pragma unroll
        for (int r = 0; r < 4; r++) {
            int d = 2*lane + 64*r;
            ev[r] = __half22float2(*(const __half2*)(ep + d));
            float2 kv = *(const float2*)(kp + d);
            vv[r] = *(const float2*)(vp + d);
            a += qr[r].x * (kv.x + ev[r].x) + qr[r].y * (kv.y + ev[r].y);
        }
#pragma unroll
        for (int dlt = 16; dlt; dlt >>= 1) a += __shfl_xor_sync(0xffffffffu, a, dlt);
        a *= 0.0625f;
        float mn = fmaxf(m, a);
        float scale = expf(m - mn);
        float w = expf(a - mn);
        den = den * scale + w;
#pragma unroll
        for (int r = 0; r < 4; r++) {
            o[r].x = o[r].x * scale + w * (vv[r].x + ev[r].x);
            o[r].y = o[r].y * scale + w * (vv[r].y + ev[r].y);
        }
        m = mn;
    }
    float invden = (deg > 0) ? (1.f / den) : 0.f;
    const float* sp = g_qkvs + (size_t)bn*QKVS_W + 3*HD + h*DD;
    __half* hhi = g_hhi + (size_t)bn*HD + h*DD;
    __half* hlo = g_hlo + (size_t)bn*HD + h*DD;
#pragma unroll
    for (int r = 0; r < 4; r++) {
        int d = 2*lane + 64*r;
        float2 sk = *(const float2*)(sp + d);
        float f0 = fmaxf(sk.x + o[r].x * invden, 0.f);
        float f1 = fmaxf(sk.y + o[r].y * invden, 0.f);
        uint32_t hw, lw;
        split2h(f0, f1, hw, lw);
        *(uint32_t*)(hhi + d) = hw;
        *(uint32_t*)(hlo + d) = lw;
    }
}

// ================= inv path =================
__global__ void mixed_inv_split_k(const int* __restrict__ tok, const int* __restrict__ nod,
                                  const float* __restrict__ emb) {
    int row = blockIdx.x, t = threadIdx.x;   // 128 threads
    int b = row / LL;
    int tk = tok[row], nd = nod[row];
    float2 f0 = *(const float2*)(emb + (size_t)tk*DD + 2*t);
    float2 f1 = *(const float2*)(g_gr + (size_t)(b*NN + nd)*DD + 2*t);
    uint32_t hw, lw;
    split2h(f0.x + f1.x, f0.y + f1.y, hw, lw);
    *(uint32_t*)(g_invehi + (size_t)row*DD + 2*t) = hw;
    *(uint32_t*)(g_invelo + (size_t)row*DD + 2*t) = lw;
}

// GRU: one block per batch, 384 threads, 2 gates/thread, W_hh fp16 packed
__global__ void gru_k(const float* __restrict__ b_hh) {
    __shared__ float hs[256];
    __shared__ float ghs[768];
    int b = blockIdx.x, t = threadIdx.x;  // 384 threads
    if (t < 256) hs[t] = 0.f;
    float bh0 = b_hh[t], bh1 = b_hh[t + 384];
    const uint4* W = (const uint4*)g_Wh8;
    __syncthreads();
    for (int l = 0; l < LL; l++) {
        float acc0 = bh0, acc1 = bh1;
#pragma unroll 8
        for (int j8 = 0; j8 < 32; j8++) {
            uint4 w0 = W[j8 * G3 + t];
            uint4 w1 = W[j8 * G3 + t + 384];
            float4 h0 = *(const float4*)(hs + 8*j8);
            float4 h1 = *(const float4*)(hs + 8*j8 + 4);
            float2 p;
            p = __half22float2(*reinterpret_cast<__half2*>(&w0.x));
            acc0 += h0.x*p.x + h0.y*p.y;
            p = __half22float2(*reinterpret_cast<__half2*>(&w0.y));
            acc0 += h0.z*p.x + h0.w*p.y;
            p = __half22float2(*reinterpret_cast<__half2*>(&w0.z));
            acc0 += h1.x*p.x + h1.y*p.y;
            p = __half22float2(*reinterpret_cast<__half2*>(&w0.w));
            acc0 += h1.z*p.x + h1.w*p.y;
            p = __half22float2(*reinterpret_cast<__half2*>(&w1.x));
            acc1 += h0.x*p.x + h0.y*p.y;
            p = __half22float2(*reinterpret_cast<__half2*>(&w1.y));
            acc1 += h0.z*p.x + h0.w*p.y;
            p = __half22float2(*reinterpret_cast<__half2*>(&w1.z));
            acc1 += h1.x*p.x + h1.y*p.y;
            p = __half22float2(*reinterpret_cast<__half2*>(&w1.w));
            acc1 += h1.z*p.x + h1.w*p.y;
        }
        ghs[t] = acc0;
        ghs[t + 384] = acc1;
        __syncthreads();
        float hn = 0.f;
        if (t < 256) {
            const float* g = g_gx + (size_t)(b*LL + l)*G3;
            float r = 1.f / (1.f + expf(-(g[t]       + ghs[t])));
            float z = 1.f / (1.f + expf(-(g[256 + t] + ghs[256 + t])));
            float c = tanhf(g[512 + t] + r * ghs[512 + t]);
            hn = (1.f - z) * c + z * hs[t];
        }
        __syncthreads();
        if (t < 256) hs[t] = hn;
        __syncthreads();
    }
    if (t < 256) g_invvec[b*OO + t] = hs[t];
}

// ================= scoring =================
__global__ void score_k(const float* __restrict__ Wap, const float* __restrict__ bap,
                        const float* __restrict__ Wab, const float* __restrict__ bab,
                        const int* __restrict__ aa_token, const int* __restrict__ aa_node,
                        const float* __restrict__ mask, const float* __restrict__ emb,
                        float* __restrict__ out) {
    __shared__ float invs[256];
    __shared__ float u[256];
    __shared__ float red[256];
    int b = blockIdx.x, t = threadIdx.x;
    int warp = t >> 5, lane = t & 31;
    invs[t] = g_invvec[b*OO + t];
    __syncthreads();
    for (int d = warp*32; d < warp*32 + 32; d++) {
        float acc = 0.f;
#pragma unroll
        for (int r = 0; r < 8; r++) {
            int o = lane + 32*r;
            acc += Wap[(size_t)d*OO + o] * invs[o];
        }
#pragma unroll
        for (int dd = 16; dd; dd >>= 1) acc += __shfl_xor_sync(0xffffffffu, acc, dd);
        if (lane == 0) u[d] = acc + Wab[d];
    }
    red[t] = bap[t] * invs[t];
    __syncthreads();
    for (int s = 128; s; s >>= 1) {
        if (t < s) red[t] += red[t + s];
        __syncthreads();
    }
    float cb = red[0] + bab[0];
    for (int a = warp; a < ACT; a += 8) {
        int tok = aa_token[b*ACT + a], nod = aa_node[b*ACT + a];
        const float* er = emb + (size_t)tok*DD;
        const float* gg = g_gr + (size_t)(b*NN + nod)*DD;
        float acc = 0.f;
#pragma unroll
        for (int r = 0; r < 8; r++) {
            int d = lane + 32*r;
            acc += (er[d] + gg[d]) * u[d];
        }
#pragma unroll
        for (int dd = 16; dd; dd >>= 1) acc += __shfl_xor_sync(0xffffffffu, acc, dd);
        if (lane == 0) {
            float mk = mask[b*ACT + a];
            float lm = fmaxf(logf(mk), -FLT_MAX);
            out[b*ACT + a] = acc + cb + lm;
        }
    }
}

// ================= host launcher =================
extern "C" void kernel_launch(void* const* d_in, const int* in_sizes, int n_in,
                              void* d_out, int out_size) {
    const int*   node_tokens = (const int*)d_in[0];
    const int*   edge_tokens = (const int*)d_in[1];
    const int*   edge_index  = (const int*)d_in[2];
    const int*   inv_token   = (const int*)d_in[3];
    const int*   inv_node    = (const int*)d_in[4];
    const int*   aa_token    = (const int*)d_in[5];
    const int*   aa_node     = (const int*)d_in[6];
    const float* action_mask = (const float*)d_in[7];
    const float* emb         = (const float*)d_in[8];
    const float* Wq  = (const float*)d_in[9];
    const float* bq  = (const float*)d_in[10];
    const float* Wk  = (const float*)d_in[11];
    const float* bk  = (const float*)d_in[12];
    const float* Wv  = (const float*)d_in[13];
    const float* bv  = (const float*)d_in[14];
    const float* We  = (const float*)d_in[15];
    const float* Wsk = (const float*)d_in[16];
    const float* bsk = (const float*)d_in[17];
    const float* W1  = (const float*)d_in[18];
    const float* b1  = (const float*)d_in[19];
    const float* Wp  = (const float*)d_in[20];
    const float* bp  = (const float*)d_in[21];
    const float* W_ih = (const float*)d_in[22];
    const float* W_hh = (const float*)d_in[23];
    const float* b_ih = (const float*)d_in[24];
    const float* b_hh = (const float*)d_in[25];
    const float* Wab = (const float*)d_in[26];
    const float* bab = (const float*)d_in[27];
    const float* Wap = (const float*)d_in[28];
    const float* bap = (const float*)d_in[29];
    float* out = (float*)d_out;

    void* p;
    __half *xhi, *xlo, *eahi, *ealo, *e_, *hhi, *hlo;
    __half *invehi, *invelo, *invhhi, *invhlo;
    __half *bN, *bE, *bw1, *bwp, *bih, *Wh8;
    float *qkvs, *gr_, *gx_, *biasN;
    cudaGetSymbolAddress(&p, g_xhi);    xhi = (__half*)p;
    cudaGetSymbolAddress(&p, g_xlo);    xlo = (__half*)p;
    cudaGetSymbolAddress(&p, g_eahi);   eahi = (__half*)p;
    cudaGetSymbolAddress(&p, g_ealo);   ealo = (__half*)p;
    cudaGetSymbolAddress(&p, g_qkvs);   qkvs = (float*)p;
    cudaGetSymbolAddress(&p, g_e);      e_ = (__half*)p;
    cudaGetSymbolAddress(&p, g_hhi);    hhi = (__half*)p;
    cudaGetSymbolAddress(&p, g_hlo);    hlo = (__half*)p;
    cudaGetSymbolAddress(&p, g_gr);     gr_ = (float*)p;
    cudaGetSymbolAddress(&p, g_invehi); invehi = (__half*)p;
    cudaGetSymbolAddress(&p, g_invelo); invelo = (__half*)p;
    cudaGetSymbolAddress(&p, g_invhhi); invhhi = (__half*)p;
    cudaGetSymbolAddress(&p, g_invhlo); invhlo = (__half*)p;
    cudaGetSymbolAddress(&p, g_gx);     gx_ = (float*)p;
    cudaGetSymbolAddress(&p, g_Wh8);    Wh8 = (__half*)p;
    cudaGetSymbolAddress(&p, g_biasN);  biasN = (float*)p;
    cudaGetSymbolAddress(&p, g_bN);     bN = (__half*)p;
    cudaGetSymbolAddress(&p, g_bE);     bE = (__half*)p;
    cudaGetSymbolAddress(&p, g_bw1);    bw1 = (__half*)p;
    cudaGetSymbolAddress(&p, g_bwp);    bwp = (__half*)p;
    cudaGetSymbolAddress(&p, g_bih);    bih = (__half*)p;

    cudaFuncSetAttribute(mmagemm_k<0,1,0>, cudaFuncAttributeMaxDynamicSharedMemorySize, GEMM_SMEM);
    cudaFuncSetAttribute(mmagemm_k<0,0,1>, cudaFuncAttributeMaxDynamicSharedMemorySize, GEMM_SMEM);
    cudaFuncSetAttribute(mmagemm_k<1,1,0>, cudaFuncAttributeMaxDynamicSharedMemorySize, GEMM_SMEM);
    cudaFuncSetAttribute(mmagemm_k<1,1,2>, cudaFuncAttributeMaxDynamicSharedMemorySize, GEMM_SMEM);

    // gathers + weight prep
    gather_split_k<<<BB*NN, 128>>>(xhi, xlo, emb, node_tokens);
    gather_split_k<<<BB*EE, 128>>>(eahi, ealo, emb, edge_tokens);
    convWTh_k<<<DD, 256>>>(We, bE, DD, HD);
    packWhh_h_k<<<G3, 32>>>(W_hh, Wh8);
    convWNh_k<<<(G3*DD + 255)/256, 256>>>(W_ih, bih, G3*DD);

    // edge projection: [64000,256] @ [256,1024] -> fp16 e
    dim3 gedge(HD/128, (BB*EE)/128);
    mmagemm_k<0,0,1><<<gedge, 256, GEMM_SMEM>>>(eahi, ealo, bE, nullptr,
                                                nullptr, e_, nullptr, nullptr, HD, DD);

    convWTh_k<<<DD, 256>>>(Wq,  bN,           DD, HD);
    convWTh_k<<<DD, 256>>>(Wk,  bN + 1024*DD, DD, HD);
    convWTh_k<<<DD, 256>>>(Wv,  bN + 2048*DD, DD, HD);
    convWTh_k<<<DD, 256>>>(Wsk, bN + 3072*DD, DD, HD);
    biascat_k<<<16, 256>>>(bq, bk, bv, bsk, biasN);

    // combined node projections: [16000,256] @ [256,4096]
    dim3 gproj(QKVS_W/128, (BB*NN)/128);
    mmagemm_k<0,1,0><<<gproj, 256, GEMM_SMEM>>>(xhi, xlo, bN, biasN,
                                                qkvs, nullptr, nullptr, nullptr, QKVS_W, DD);

    // CSR over dst
    zero_cnt_k<<<(BB*NN + 255)/256, 256>>>();
    count_k<<<(BB*EE + 255)/256, 256>>>(edge_index);
    scan_k<<<BB, 32>>>();
    fill_k<<<(BB*EE + 255)/256, 256>>>(edge_index);

    // fused attention + skip + relu + split
    attn_fused_k<<<(BB*NN*NH + 3)/4, 128>>>(edge_index);

    // graph_repr = relu(h@W1 + b1)
    convWTh_k<<<HD, 256>>>(W1, bw1, HD, DD);
    dim3 ggr(DD/128, (BB*NN)/128);
    mmagemm_k<1,1,0><<<ggr, 256, GEMM_SMEM>>>(hhi, hlo, bw1, b1,
                                              gr_, nullptr, nullptr, nullptr, DD, HD);

    // inv path
    mixed_inv_split_k<<<BB*LL, 128>>>(inv_token, inv_node, emb);
    convWTh_k<<<DD, 256>>>(Wp, bwp, DD, DD);
    dim3 ginv(DD/128, (BB*LL)/128);
    mmagemm_k<1,1,2><<<ginv, 256, GEMM_SMEM>>>(invehi, invelo, bwp, bp,
                                               nullptr, nullptr, invhhi, invhlo, DD, DD);
    dim3 ggx(G3/128, (BB*LL)/128);
    mmagemm_k<0,1,0><<<ggx, 256, GEMM_SMEM>>>(invhhi, invhlo, bih, b_ih,
                                              gx_, nullptr, nullptr, nullptr, G3, DD);
    gru_k<<<BB, 384>>>(b_hh);

    // scores
    score_k<<<BB, 256>>>(Wap, bap, Wab, bab, aa_token, aa_node, action_mask, emb, out);
    (void)in_sizes; (void)n_in; (void)out_size;
}

// round 10
// speedup vs baseline: 1.6246x; 1.2200x over previous
#include <cuda_runtime.h>
#include <cuda_fp16.h>
#include <math.h>
#include <float.h>
#include <stdint.h>

// Problem constants
#define BB 16
#define NN 1000
#define EE 4000
#define DD 256
#define NH 4
#define HD 1024
#define LL 64
#define ACT 128
#define OO 256
#define G3 768
#define QKVS_W 4096

// ================= scratch (device globals) =================
__device__ __align__(16) __half g_x[BB*NN*DD];
__device__ __align__(16) __half g_ea[BB*EE*DD];
__device__ __align__(16) __half g_qkvs[(size_t)BB*NN*QKVS_W];  // q|k|v|skip fp16
__device__ __align__(16) __half g_e[(size_t)BB*EE*HD];         // fp16 edge proj
__device__ __align__(16) __half g_h[(size_t)BB*NN*HD];
__device__ __align__(16) float g_gr[BB*NN*DD];
__device__ int   g_cnt[BB*NN];
__device__ int   g_off[BB*NN];
__device__ int   g_cur[BB*NN];
__device__ int   g_eord[BB*EE];
__device__ __align__(16) __half g_inve[BB*LL*DD];
__device__ __align__(16) __half g_invh[BB*LL*DD];
__device__ __align__(16) float g_gx[BB*LL*G3];
__device__ __align__(16) __half g_Wh8[DD*G3];   // W_hh fp16 packed (j8, g, 8)
__device__ float g_invvec[BB*OO];
__device__ float g_biasN[QKVS_W];
// fp16 weight buffers, [N,K] layout (k contiguous)
__device__ __align__(16) __half g_bN[QKVS_W*DD];
__device__ __align__(16) __half g_bE[HD*DD];
__device__ __align__(16) __half g_bw1[DD*HD];
__device__ __align__(16) __half g_bwp[DD*DD];
__device__ __align__(16) __half g_bih[G3*DD];

// ================= helpers =================
__device__ __forceinline__ uint32_t smem_to_u32(const void* smem_ptr) {
    uint32_t addr;
    asm("{ .reg .u64 tmp; cvta.to.shared.u64 tmp, %1; cvt.u32.u64 %0, tmp; }"
        : "=r"(addr) : "l"(smem_ptr));
    return addr;
}
__device__ __forceinline__ void ldsm4(uint32_t r[4], uint32_t addr) {
    asm volatile("ldmatrix.sync.aligned.m8n8.x4.shared.b16 {%0,%1,%2,%3}, [%4];"
        : "=r"(r[0]), "=r"(r[1]), "=r"(r[2]), "=r"(r[3]) : "r"(addr));
}
__device__ __forceinline__ void mma16816h(float c[4], uint32_t a0, uint32_t a1,
                                          uint32_t a2, uint32_t a3,
                                          uint32_t b0, uint32_t b1) {
    asm volatile(
        "mma.sync.aligned.m16n8k16.row.col.f32.f16.f16.f32 "
        "{%0,%1,%2,%3}, {%4,%5,%6,%7}, {%8,%9}, {%0,%1,%2,%3};"
        : "+f"(c[0]), "+f"(c[1]), "+f"(c[2]), "+f"(c[3])
        : "r"(a0), "r"(a1), "r"(a2), "r"(a3), "r"(b0), "r"(b1));
}
__device__ __forceinline__ void cpasync16(uint32_t dst, const void* src) {
    asm volatile("cp.async.cg.shared.global [%0], [%1], 16;" :: "r"(dst), "l"(src));
}
__device__ __forceinline__ void cp_commit() {
    asm volatile("cp.async.commit_group;");
}
template<int N> __device__ __forceinline__ void cp_wait() {
    asm volatile("cp.async.wait_group %0;" :: "n"(N));
}

// ================= gathers / conversions =================
__global__ void gather_h_k(__half* __restrict__ dst, const float* __restrict__ emb,
                           const int* __restrict__ idx) {
    int row = blockIdx.x, t = threadIdx.x;   // 64 threads, 4 elems each
    int tok = idx[row];
    float4 f = *(const float4*)(emb + (size_t)tok*DD + 4*t);
    __half2 p0 = __floats2half2_rn(f.x, f.y);
    __half2 p1 = __floats2half2_rn(f.z, f.w);
    uint2 o;
    o.x = *reinterpret_cast<uint32_t*>(&p0);
    o.y = *reinterpret_cast<uint32_t*>(&p1);
    *(uint2*)(dst + (size_t)row*DD + 4*t) = o;
}
// pack W_hh[768,256] fp32 -> fp16 W8[(j/8)*768 + g][8]
__global__ void packWhh_h_k(const float* __restrict__ Whh, __half* __restrict__ W8) {
    int g = blockIdx.x, j8 = threadIdx.x;   // 768 blocks, 32 threads
    float4 a = *(const float4*)(Whh + (size_t)g*DD + 8*j8);
    float4 b = *(const float4*)(Whh + (size_t)g*DD + 8*j8 + 4);
    __half2 h0 = __floats2half2_rn(a.x, a.y);
    __half2 h1 = __floats2half2_rn(a.z, a.w);
    __half2 h2 = __floats2half2_rn(b.x, b.y);
    __half2 h3 = __floats2half2_rn(b.z, b.w);
    uint4 o;
    o.x = *reinterpret_cast<uint32_t*>(&h0);
    o.y = *reinterpret_cast<uint32_t*>(&h1);
    o.z = *reinterpret_cast<uint32_t*>(&h2);
    o.w = *reinterpret_cast<uint32_t*>(&h3);
    *(uint4*)(W8 + ((size_t)j8*G3 + g)*8) = o;
}
// tiled transpose-convert: W[K,N] fp32 -> bh[N,K] fp16. block (32,8), grid (K/32, N/32)
__global__ void convT_k(const float* __restrict__ W, __half* __restrict__ bh,
                        int K, int N) {
    __shared__ float tile[32][33];
    int k0 = blockIdx.x * 32, n0 = blockIdx.y * 32;
    int tx = threadIdx.x, ty = threadIdx.y;
#pragma unroll
    for (int j = 0; j < 4; j++)
        tile[ty + 8*j][tx] = W[(size_t)(k0 + ty + 8*j) * N + n0 + tx];
    __syncthreads();
#pragma unroll
    for (int j = 0; j < 4; j++)
        bh[(size_t)(n0 + ty + 8*j) * K + k0 + tx] = __float2half_rn(tile[tx][ty + 8*j]);
}
__global__ void convWNh_k(const float* __restrict__ W, __half* __restrict__ bh, int total) {
    int i = blockIdx.x * blockDim.x + threadIdx.x;
    if (i < total) bh[i] = __float2half_rn(W[i]);
}
__global__ void biascat_k(const float* __restrict__ b0, const float* __restrict__ b1,
                          const float* __restrict__ b2, const float* __restrict__ b3,
                          float* __restrict__ o) {
    int t = blockIdx.x * 256 + threadIdx.x;
    const float* src = (t < 1024) ? b0 : (t < 2048) ? b1 : (t < 3072) ? b2 : b3;
    o[t] = src[t & 1023];
}

// ================= single-pass fp16 mma GEMM =================
// C[M,N] = act(A@B^T + bias); A fp16 [M,K], B fp16 [N,K].
// CTA 128x128, 8 warps, warp tile 64x32, K chunk 32, 4-stage cp.async pipeline.
// OUTMODE: 0 = fp32 C, 1 = fp16 Ch.
#define KC 32
#define RSB 80
#define STG_A 0
#define STG_B 10240
#define STAGE_SZ 20480
#define NSTAGE 4
#define GEMM_SMEM (NSTAGE*STAGE_SZ)

template<int CRELU, int HASBIAS, int OUTMODE>
__global__ __launch_bounds__(256, 1) void mmagemm_k(
    const __half* __restrict__ A, const __half* __restrict__ Bw,
    const float* __restrict__ bias, float* __restrict__ C,
    __half* __restrict__ Ch, int Nld, int K) {
    extern __shared__ char smc[];
    const uint32_t smb = smem_to_u32(smc);
    const int t = threadIdx.x, lane = t & 31, warp = t >> 5;
    const int bm = blockIdx.y * 128, bn = blockIdx.x * 128;
    const int wm = (warp >> 2) * 64, wn = (warp & 3) * 32;

    const int fr = t >> 1, fk = (t & 1) * 16;
    const __half* Ap = A  + (size_t)(bm + fr) * K + fk;
    const __half* Bp = Bw + (size_t)(bn + fr) * K + fk;
    const uint32_t fillOff = smb + (uint32_t)(fr * RSB + fk * 2);

    const uint32_t aBase = smb + (uint32_t)(wm + (lane & 15)) * RSB + (uint32_t)(lane >> 4) * 16;
    const uint32_t bBase = smb + (uint32_t)(wn + ((lane >> 4) << 3) + (lane & 7)) * RSB
                               + (uint32_t)((lane >> 3) & 1) * 16;

    float acc[4][4][4];
#pragma unroll
    for (int i = 0; i < 4; i++)
#pragma unroll
        for (int j = 0; j < 4; j++)
#pragma unroll
            for (int k = 0; k < 4; k++) acc[i][j][k] = 0.f;

    const int NC = K / KC;
#pragma unroll
    for (int c = 0; c < NSTAGE - 1; c++) {
        uint32_t d = fillOff + (uint32_t)(c * STAGE_SZ);
        const __half* a0 = Ap + c * KC;
        const __half* b0 = Bp + c * KC;
        cpasync16(d + STG_A,      a0);
        cpasync16(d + STG_A + 16, a0 + 8);
        cpasync16(d + STG_B,      b0);
        cpasync16(d + STG_B + 16, b0 + 8);
        cp_commit();
    }

    for (int c = 0; c < NC; c++) {
        cp_wait<NSTAGE - 2>();
        __syncthreads();
        const uint32_t stg = (uint32_t)((c & (NSTAGE - 1)) * STAGE_SZ);
#pragma unroll
        for (int ks = 0; ks < 2; ks++) {
            const uint32_t kb = (uint32_t)(ks * 32);
            uint32_t br[2][4];
#pragma unroll
            for (int nb = 0; nb < 2; nb++)
                ldsm4(br[nb], bBase + stg + STG_B + (uint32_t)(nb * 16 * RSB) + kb);
            uint32_t ar[4][4];
#pragma unroll
            for (int mi = 0; mi < 4; mi++)
                ldsm4(ar[mi], aBase + stg + STG_A + (uint32_t)(mi * 16 * RSB) + kb);
#pragma unroll
            for (int mi = 0; mi < 4; mi++)
#pragma unroll
                for (int ni = 0; ni < 4; ni++)
                    mma16816h(acc[mi][ni], ar[mi][0], ar[mi][1], ar[mi][2], ar[mi][3],
                              br[ni>>1][(ni&1)*2], br[ni>>1][(ni&1)*2+1]);
        }
        __syncthreads();
        const int nx = c + NSTAGE - 1;
        if (nx < NC) {
            uint32_t d = fillOff + (uint32_t)((nx & (NSTAGE - 1)) * STAGE_SZ);
            const __half* a0 = Ap + nx * KC;
            const __half* b0 = Bp + nx * KC;
            cpasync16(d + STG_A,      a0);
            cpasync16(d + STG_A + 16, a0 + 8);
            cpasync16(d + STG_B,      b0);
            cpasync16(d + STG_B + 16, b0 + 8);
        }
        cp_commit();
    }

#pragma unroll
    for (int mi = 0; mi < 4; mi++) {
        const int r0 = bm + wm + mi*16 + (lane >> 2);
#pragma unroll
        for (int ni = 0; ni < 4; ni++) {
            const int col = bn + wn + ni*8 + (lane & 3)*2;
            float bx = 0.f, by = 0.f;
            if (HASBIAS) { bx = bias[col]; by = bias[col+1]; }
            float v0 = acc[mi][ni][0] + bx, v1 = acc[mi][ni][1] + by;
            float v2 = acc[mi][ni][2] + bx, v3 = acc[mi][ni][3] + by;
            if (CRELU) {
                v0 = fmaxf(v0, 0.f); v1 = fmaxf(v1, 0.f);
                v2 = fmaxf(v2, 0.f); v3 = fmaxf(v3, 0.f);
            }
            if (OUTMODE == 0) {
                *(float2*)(C + (size_t)r0 * Nld + col) = make_float2(v0, v1);
                *(float2*)(C + (size_t)(r0+8) * Nld + col) = make_float2(v2, v3);
            } else {
                __half2 p0 = __floats2half2_rn(v0, v1);
                __half2 p1 = __floats2half2_rn(v2, v3);
                *(uint32_t*)(Ch + (size_t)r0 * Nld + col) = *reinterpret_cast<uint32_t*>(&p0);
                *(uint32_t*)(Ch + (size_t)(r0+8) * Nld + col) = *reinterpret_cast<uint32_t*>(&p1);
            }
        }
    }
}

// ================= CSR build over dst =================
__global__ void zero_cnt_k() {
    int i = blockIdx.x * blockDim.x + threadIdx.x;
    if (i < BB*NN) g_cnt[i] = 0;
}
__global__ void count_k(const int* __restrict__ ei) {
    int i = blockIdx.x * blockDim.x + threadIdx.x;
    if (i >= BB*EE) return;
    int b = i / EE, e = i % EE;
    int dst = ei[(b*2 + 1)*EE + e];
    atomicAdd(&g_cnt[b*NN + dst], 1);
}
__global__ void scan_k() {
    int b = blockIdx.x;
    if (threadIdx.x == 0) {
        int run = 0;
        for (int n = 0; n < NN; n++) {
            g_off[b*NN + n] = run;
            g_cur[b*NN + n] = run;
            run += g_cnt[b*NN + n];
        }
    }
}
__global__ void fill_k(const int* __restrict__ ei) {
    int i = blockIdx.x * blockDim.x + threadIdx.x;
    if (i >= BB*EE) return;
    int b = i / EE, e = i % EE;
    int dst = ei[(b*2 + 1)*EE + e];
    int pos = atomicAdd(&g_cur[b*NN + dst], 1);
    g_eord[b*EE + pos] = e;
}

// ================= fused attention (online softmax), all fp16 inputs =================
__global__ void attn_fused_k(const int* __restrict__ ei) {
    int g = blockIdx.x * 4 + (threadIdx.x >> 5);
    int lane = threadIdx.x & 31;
    if (g >= BB*NN*NH) return;
    int h = g & 3, bn = g >> 2;
    int b = bn / NN;
    int deg = g_cnt[bn], off = g_off[bn];

    const __half* qp = g_qkvs + (size_t)bn*QKVS_W + h*DD;
    float2 qr[4];
#pragma unroll
    for (int r = 0; r < 4; r++)
        qr[r] = __half22float2(*(const __half2*)(qp + 2*lane + 64*r));

    float m = -3.0e38f, den = 0.f;
    float2 o[4];
#pragma unroll
    for (int r = 0; r < 4; r++) o[r] = make_float2(0.f, 0.f);

    for (int i = 0; i < deg; i++) {
        int e = g_eord[b*EE + off + i];
        int src = ei[(b*2)*EE + e];
        const __half* base = g_qkvs + (size_t)(b*NN + src)*QKVS_W;
        const __half* kp = base + HD + h*DD;
        const __half* vp = base + 2*HD + h*DD;
        const __half* ep = g_e + (size_t)(b*EE + e)*HD + h*DD;
        float2 ev[4], vv[4];
        float a = 0.f;
#pragma unroll
        for (int r = 0; r < 4; r++) {
            int d = 2*lane + 64*r;
            ev[r] = __half22float2(*(const __half2*)(ep + d));
            float2 kv = __half22float2(*(const __half2*)(kp + d));
            vv[r] = __half22float2(*(const __half2*)(vp + d));
            a += qr[r].x * (kv.x + ev[r].x) + qr[r].y * (kv.y + ev[r].y);
        }
#pragma unroll
        for (int dlt = 16; dlt; dlt >>= 1) a += __shfl_xor_sync(0xffffffffu, a, dlt);
        a *= 0.0625f;
        float mn = fmaxf(m, a);
        float scale = expf(m - mn);
        float w = expf(a - mn);
        den = den * scale + w;
#pragma unroll
        for (int r = 0; r < 4; r++) {
            o[r].x = o[r].x * scale + w * (vv[r].x + ev[r].x);
            o[r].y = o[r].y * scale + w * (vv[r].y + ev[r].y);
        }
        m = mn;
    }
    float invden = (deg > 0) ? (1.f / den) : 0.f;
    const __half* sp = g_qkvs + (size_t)bn*QKVS_W + 3*HD + h*DD;
    __half* hp = g_h + (size_t)bn*HD + h*DD;
#pragma unroll
    for (int r = 0; r < 4; r++) {
        int d = 2*lane + 64*r;
        float2 sk = __half22float2(*(const __half2*)(sp + d));
        float f0 = fmaxf(sk.x + o[r].x * invden, 0.f);
        float f1 = fmaxf(sk.y + o[r].y * invden, 0.f);
        __half2 hv = __floats2half2_rn(f0, f1);
        *(uint32_t*)(hp + d) = *reinterpret_cast<uint32_t*>(&hv);
    }
}

// ================= inv path =================
__global__ void mixed_inv_k(const int* __restrict__ tok, const int* __restrict__ nod,
                            const float* __restrict__ emb) {
    int row = blockIdx.x, t = threadIdx.x;   // 128 threads
    int b = row / LL;
    int tk = tok[row], nd = nod[row];
    float2 f0 = *(const float2*)(emb + (size_t)tk*DD + 2*t);
    float2 f1 = *(const float2*)(g_gr + (size_t)(b*NN + nd)*DD + 2*t);
    __half2 hv = __floats2half2_rn(f0.x + f1.x, f0.y + f1.y);
    *(uint32_t*)(g_inve + (size_t)row*DD + 2*t) = *reinterpret_cast<uint32_t*>(&hv);
}

// GRU: one block per batch, 384 threads, 2 gates/thread, W_hh fp16 packed
__global__ void gru_k(const float* __restrict__ b_hh) {
    __shared__ float hs[256];
    __shared__ float ghs[768];
    int b = blockIdx.x, t = threadIdx.x;  // 384 threads
    if (t < 256) hs[t] = 0.f;
    float bh0 = b_hh[t], bh1 = b_hh[t + 384];
    const uint4* W = (const uint4*)g_Wh8;
    __syncthreads();
    for (int l = 0; l < LL; l++) {
        float acc0 = bh0, acc1 = bh1;
#pragma unroll 8
        for (int j8 = 0; j8 < 32; j8++) {
            uint4 w0 = W[j8 * G3 + t];
            uint4 w1 = W[j8 * G3 + t + 384];
            float4 h0 = *(const float4*)(hs + 8*j8);
            float4 h1 = *(const float4*)(hs + 8*j8 + 4);
            float2 p;
            p = __half22float2(*reinterpret_cast<__half2*>(&w0.x));
            acc0 += h0.x*p.x + h0.y*p.y;
            p = __half22float2(*reinterpret_cast<__half2*>(&w0.y));
            acc0 += h0.z*p.x + h0.w*p.y;
            p = __half22float2(*reinterpret_cast<__half2*>(&w0.z));
            acc0 += h1.x*p.x + h1.y*p.y;
            p = __half22float2(*reinterpret_cast<__half2*>(&w0.w));
            acc0 += h1.z*p.x + h1.w*p.y;
            p = __half22float2(*reinterpret_cast<__half2*>(&w1.x));
            acc1 += h0.x*p.x + h0.y*p.y;
            p = __half22float2(*reinterpret_cast<__half2*>(&w1.y));
            acc1 += h0.z*p.x + h0.w*p.y;
            p = __half22float2(*reinterpret_cast<__half2*>(&w1.z));
            acc1 += h1.x*p.x + h1.y*p.y;
            p = __half22float2(*reinterpret_cast<__half2*>(&w1.w));
            acc1 += h1.z*p.x + h1.w*p.y;
        }
        ghs[t] = acc0;
        ghs[t + 384] = acc1;
        __syncthreads();
        float hn = 0.f;
        if (t < 256) {
            const float* g = g_gx + (size_t)(b*LL + l)*G3;
            float r = 1.f / (1.f + expf(-(g[t]       + ghs[t])));
            float z = 1.f / (1.f + expf(-(g[256 + t] + ghs[256 + t])));
            float c = tanhf(g[512 + t] + r * ghs[512 + t]);
            hn = (1.f - z) * c + z * hs[t];
        }
        __syncthreads();
        if (t < 256) hs[t] = hn;
        __syncthreads();
    }
    if (t < 256) g_invvec[b*OO + t] = hs[t];
}

// ================= scoring =================
__global__ void score_k(const float* __restrict__ Wap, const float* __restrict__ bap,
                        const float* __restrict__ Wab, const float* __restrict__ bab,
                        const int* __restrict__ aa_token, const int* __restrict__ aa_node,
                        const float* __restrict__ mask, const float* __restrict__ emb,
                        float* __restrict__ out) {
    __shared__ float invs[256];
    __shared__ float u[256];
    __shared__ float red[256];
    int b = blockIdx.x, t = threadIdx.x;
    int warp = t >> 5, lane = t & 31;
    invs[t] = g_invvec[b*OO + t];
    __syncthreads();
    for (int d = warp*32; d < warp*32 + 32; d++) {
        float acc = 0.f;
#pragma unroll
        for (int r = 0; r < 8; r++) {
            int o = lane + 32*r;
            acc += Wap[(size_t)d*OO + o] * invs[o];
        }
#pragma unroll
        for (int dd = 16; dd; dd >>= 1) acc += __shfl_xor_sync(0xffffffffu, acc, dd);
        if (lane == 0) u[d] = acc + Wab[d];
    }
    red[t] = bap[t] * invs[t];
    __syncthreads();
    for (int s = 128; s; s >>= 1) {
        if (t < s) red[t] += red[t + s];
        __syncthreads();
    }
    float cb = red[0] + bab[0];
    for (int a = warp; a < ACT; a += 8) {
        int tok = aa_token[b*ACT + a], nod = aa_node[b*ACT + a];
        const float* er = emb + (size_t)tok*DD;
        const float* gg = g_gr + (size_t)(b*NN + nod)*DD;
        float acc = 0.f;
#pragma unroll
        for (int r = 0; r < 8; r++) {
            int d = lane + 32*r;
            acc += (er[d] + gg[d]) * u[d];
        }
#pragma unroll
        for (int dd = 16; dd; dd >>= 1) acc += __shfl_xor_sync(0xffffffffu, acc, dd);
        if (lane == 0) {
            float mk = mask[b*ACT + a];
            float lm = fmaxf(logf(mk), -FLT_MAX);
            out[b*ACT + a] = acc + cb + lm;
        }
    }
}

// ================= host launcher =================
extern "C" void kernel_launch(void* const* d_in, const int* in_sizes, int n_in,
                              void* d_out, int out_size) {
    const int*   node_tokens = (const int*)d_in[0];
    const int*   edge_tokens = (const int*)d_in[1];
    const int*   edge_index  = (const int*)d_in[2];
    const int*   inv_token   = (const int*)d_in[3];
    const int*   inv_node    = (const int*)d_in[4];
    const int*   aa_token    = (const int*)d_in[5];
    const int*   aa_node     = (const int*)d_in[6];
    const float* action_mask = (const float*)d_in[7];
    const float* emb         = (const float*)d_in[8];
    const float* Wq  = (const float*)d_in[9];
    const float* bq  = (const float*)d_in[10];
    const float* Wk  = (const float*)d_in[11];
    const float* bk  = (const float*)d_in[12];
    const float* Wv  = (const float*)d_in[13];
    const float* bv  = (const float*)d_in[14];
    const float* We  = (const float*)d_in[15];
    const float* Wsk = (const float*)d_in[16];
    const float* bsk = (const float*)d_in[17];
    const float* W1  = (const float*)d_in[18];
    const float* b1  = (const float*)d_in[19];
    const float* Wp  = (const float*)d_in[20];
    const float* bp  = (const float*)d_in[21];
    const float* W_ih = (const float*)d_in[22];
    const float* W_hh = (const float*)d_in[23];
    const float* b_ih = (const float*)d_in[24];
    const float* b_hh = (const float*)d_in[25];
    const float* Wab = (const float*)d_in[26];
    const float* bab = (const float*)d_in[27];
    const float* Wap = (const float*)d_in[28];
    const float* bap = (const float*)d_in[29];
    float* out = (float*)d_out;

    void* p;
    __half *x_, *ea_, *qkvs, *e_, *h_, *inve_, *invh_;
    __half *bN, *bE, *bw1, *bwp, *bih, *Wh8;
    float *gr_, *gx_, *biasN;
    cudaGetSymbolAddress(&p, g_x);     x_ = (__half*)p;
    cudaGetSymbolAddress(&p, g_ea);    ea_ = (__half*)p;
    cudaGetSymbolAddress(&p, g_qkvs);  qkvs = (__half*)p;
    cudaGetSymbolAddress(&p, g_e);     e_ = (__half*)p;
    cudaGetSymbolAddress(&p, g_h);     h_ = (__half*)p;
    cudaGetSymbolAddress(&p, g_gr);    gr_ = (float*)p;
    cudaGetSymbolAddress(&p, g_inve);  inve_ = (__half*)p;
    cudaGetSymbolAddress(&p, g_invh);  invh_ = (__half*)p;
    cudaGetSymbolAddress(&p, g_gx);    gx_ = (float*)p;
    cudaGetSymbolAddress(&p, g_Wh8);   Wh8 = (__half*)p;
    cudaGetSymbolAddress(&p, g_biasN); biasN = (float*)p;
    cudaGetSymbolAddress(&p, g_bN);    bN = (__half*)p;
    cudaGetSymbolAddress(&p, g_bE);    bE = (__half*)p;
    cudaGetSymbolAddress(&p, g_bw1);   bw1 = (__half*)p;
    cudaGetSymbolAddress(&p, g_bwp);   bwp = (__half*)p;
    cudaGetSymbolAddress(&p, g_bih);   bih = (__half*)p;

    cudaFuncSetAttribute(mmagemm_k<0,1,0>, cudaFuncAttributeMaxDynamicSharedMemorySize, GEMM_SMEM);
    cudaFuncSetAttribute(mmagemm_k<0,1,1>, cudaFuncAttributeMaxDynamicSharedMemorySize, GEMM_SMEM);
    cudaFuncSetAttribute(mmagemm_k<0,0,1>, cudaFuncAttributeMaxDynamicSharedMemorySize, GEMM_SMEM);
    cudaFuncSetAttribute(mmagemm_k<1,1,0>, cudaFuncAttributeMaxDynamicSharedMemorySize, GEMM_SMEM);
    cudaFuncSetAttribute(mmagemm_k<1,1,1>, cudaFuncAttributeMaxDynamicSharedMemorySize, GEMM_SMEM);

    // gathers + weight prep
    gather_h_k<<<BB*NN, 64>>>(x_, emb, node_tokens);
    gather_h_k<<<BB*EE, 64>>>(ea_, emb, edge_tokens);
    convT_k<<<dim3(DD/32, HD/32), dim3(32,8)>>>(We, bE, DD, HD);
    packWhh_h_k<<<G3, 32>>>(W_hh, Wh8);
    convWNh_k<<<(G3*DD + 255)/256, 256>>>(W_ih, bih, G3*DD);

    // edge projection: [64000,256] @ [256,1024] -> fp16 e
    dim3 gedge(HD/128, (BB*EE)/128);
    mmagemm_k<0,0,1><<<gedge, 256, GEMM_SMEM>>>(ea_, bE, nullptr, nullptr, e_, HD, DD);

    convT_k<<<dim3(DD/32, HD/32), dim3(32,8)>>>(Wq,  bN,           DD, HD);
    convT_k<<<dim3(DD/32, HD/32), dim3(32,8)>>>(Wk,  bN + 1024*DD, DD, HD);
    convT_k<<<dim3(DD/32, HD/32), dim3(32,8)>>>(Wv,  bN + 2048*DD, DD, HD);
    convT_k<<<dim3(DD/32, HD/32), dim3(32,8)>>>(Wsk, bN + 3072*DD, DD, HD);
    biascat_k<<<16, 256>>>(bq, bk, bv, bsk, biasN);

    // combined node projections: [16000,256] @ [256,4096] -> fp16 qkvs
    dim3 gproj(QKVS_W/128, (BB*NN)/128);
    mmagemm_k<0,1,1><<<gproj, 256, GEMM_SMEM>>>(x_, bN, biasN, nullptr, qkvs, QKVS_W, DD);

    // CSR over dst
    zero_cnt_k<<<(BB*NN + 255)/256, 256>>>();
    count_k<<<(BB*EE + 255)/256, 256>>>(edge_index);
    scan_k<<<BB, 32>>>();
    fill_k<<<(BB*EE + 255)/256, 256>>>(edge_index);

    // fused attention + skip + relu -> fp16 h
    attn_fused_k<<<(BB*NN*NH + 3)/4, 128>>>(edge_index);

    // graph_repr = relu(h@W1 + b1) -> fp32 gr
    convT_k<<<dim3(HD/32, DD/32), dim3(32,8)>>>(W1, bw1, HD, DD);
    dim3 ggr(DD/128, (BB*NN)/128);
    mmagemm_k<1,1,0><<<ggr, 256, GEMM_SMEM>>>(h_, bw1, b1, gr_, nullptr, DD, HD);

    // inv path
    mixed_inv_k<<<BB*LL, 128>>>(inv_token, inv_node, emb);
    convT_k<<<dim3(DD/32, DD/32), dim3(32,8)>>>(Wp, bwp, DD, DD);
    dim3 ginv(DD/128, (BB*LL)/128);
    mmagemm_k<1,1,1><<<ginv, 256, GEMM_SMEM>>>(inve_, bwp, bp, nullptr, invh_, DD, DD);
    dim3 ggx(G3/128, (BB*LL)/128);
    mmagemm_k<0,1,0><<<ggx, 256, GEMM_SMEM>>>(invh_, bih, b_ih, gx_, nullptr, G3, DD);
    gru_k<<<BB, 384>>>(b_hh);

    // scores
    score_k<<<BB, 256>>>(Wap, bap, Wab, bab, aa_token, aa_node, action_mask, emb, out);
    (void)in_sizes; (void)n_in; (void)out_size;
}

// round 11
// speedup vs baseline: 1.7872x; 1.1001x over previous
#include <cuda_runtime.h>
#include <cuda_fp16.h>
#include <math.h>
#include <float.h>
#include <stdint.h>

// Problem constants
#define BB 16
#define NN 1000
#define EE 4000
#define DD 256
#define NH 4
#define HD 1024
#define LL 64
#define ACT 128
#define OO 256
#define G3 768
#define QKVS_W 4096

// ================= scratch (device globals) =================
__device__ __align__(16) __half g_x[BB*NN*DD];
__device__ __align__(16) __half g_ea[BB*EE*DD];
__device__ __align__(16) __half g_qkvs[(size_t)BB*NN*QKVS_W];  // q|k|v|skip fp16
__device__ __align__(16) __half g_e[(size_t)BB*EE*HD];
__device__ __align__(16) __half g_h[(size_t)BB*NN*HD];
__device__ __align__(16) float g_gr[BB*NN*DD];
__device__ int   g_cnt[BB*NN];
__device__ int   g_off[BB*NN];
__device__ int   g_cur[BB*NN];
__device__ int   g_eord[BB*EE];
__device__ __align__(16) __half g_inve[BB*LL*DD];
__device__ __align__(16) __half g_invh[BB*LL*DD];
__device__ __align__(16) float g_gx[BB*LL*G3];
__device__ __align__(16) __half g_Wh8[DD*G3];   // W_hh fp16 packed (j8, g, 8)
__device__ float g_invvec[BB*OO];
__device__ float g_biasN[QKVS_W];
// fp16 weight buffers, [N,K] layout (k contiguous)
__device__ __align__(16) __half g_bN[QKVS_W*DD];
__device__ __align__(16) __half g_bE[HD*DD];
__device__ __align__(16) __half g_bw1[DD*HD];
__device__ __align__(16) __half g_bwp[DD*DD];
__device__ __align__(16) __half g_bih[G3*DD];

// ================= helpers =================
__device__ __forceinline__ uint32_t smem_to_u32(const void* smem_ptr) {
    uint32_t addr;
    asm("{ .reg .u64 tmp; cvta.to.shared.u64 tmp, %1; cvt.u32.u64 %0, tmp; }"
        : "=r"(addr) : "l"(smem_ptr));
    return addr;
}
__device__ __forceinline__ void ldsm4(uint32_t r[4], uint32_t addr) {
    asm volatile("ldmatrix.sync.aligned.m8n8.x4.shared.b16 {%0,%1,%2,%3}, [%4];"
        : "=r"(r[0]), "=r"(r[1]), "=r"(r[2]), "=r"(r[3]) : "r"(addr));
}
__device__ __forceinline__ void mma16816h(float c[4], uint32_t a0, uint32_t a1,
                                          uint32_t a2, uint32_t a3,
                                          uint32_t b0, uint32_t b1) {
    asm volatile(
        "mma.sync.aligned.m16n8k16.row.col.f32.f16.f16.f32 "
        "{%0,%1,%2,%3}, {%4,%5,%6,%7}, {%8,%9}, {%0,%1,%2,%3};"
        : "+f"(c[0]), "+f"(c[1]), "+f"(c[2]), "+f"(c[3])
        : "r"(a0), "r"(a1), "r"(a2), "r"(a3), "r"(b0), "r"(b1));
}
__device__ __forceinline__ void cpasync16(uint32_t dst, const void* src) {
    asm volatile("cp.async.cg.shared.global [%0], [%1], 16;" :: "r"(dst), "l"(src));
}
__device__ __forceinline__ void cp_commit() {
    asm volatile("cp.async.commit_group;");
}
template<int N> __device__ __forceinline__ void cp_wait() {
    asm volatile("cp.async.wait_group %0;" :: "n"(N));
}
__device__ __forceinline__ void unpack8(const uint4& w, float* f) {
    float2 p;
    p = __half22float2(*reinterpret_cast<const __half2*>(&w.x)); f[0]=p.x; f[1]=p.y;
    p = __half22float2(*reinterpret_cast<const __half2*>(&w.y)); f[2]=p.x; f[3]=p.y;
    p = __half22float2(*reinterpret_cast<const __half2*>(&w.z)); f[4]=p.x; f[5]=p.y;
    p = __half22float2(*reinterpret_cast<const __half2*>(&w.w)); f[6]=p.x; f[7]=p.y;
}

// ================= mega prep kernel (role by blockIdx range) =================
#define PB_ZERO 63
#define PB_GX   4000
#define PB_GEA  16000
#define PB_CVT  256
#define PB_W1   256
#define PB_WP   64
#define PB_IH   768
#define PB_WHH  96
#define PB_BIAS 16

__device__ __forceinline__ void convT_body(const float* __restrict__ W,
                                           __half* __restrict__ bh,
                                           int K, int N, int k0, int n0, int t) {
    __shared__ float tile[32][33];
    int tx = t & 31, ty = t >> 5;
#pragma unroll
    for (int j = 0; j < 4; j++)
        tile[ty + 8*j][tx] = W[(size_t)(k0 + ty + 8*j) * N + n0 + tx];
    __syncthreads();
#pragma unroll
    for (int j = 0; j < 4; j++)
        bh[(size_t)(n0 + ty + 8*j) * K + k0 + tx] = __float2half_rn(tile[tx][ty + 8*j]);
}
__device__ __forceinline__ void gather_body(__half* __restrict__ dst,
                                            const float* __restrict__ emb,
                                            const int* __restrict__ idx,
                                            int row, int lt) {
    int tok = idx[row];
    float4 f = *(const float4*)(emb + (size_t)tok*DD + 4*lt);
    __half2 p0 = __floats2half2_rn(f.x, f.y);
    __half2 p1 = __floats2half2_rn(f.z, f.w);
    uint2 o;
    o.x = *reinterpret_cast<uint32_t*>(&p0);
    o.y = *reinterpret_cast<uint32_t*>(&p1);
    *(uint2*)(dst + (size_t)row*DD + 4*lt) = o;
}

__global__ void prep_k(const int* __restrict__ node_tokens, const int* __restrict__ edge_tokens,
                       const float* __restrict__ emb,
                       const float* __restrict__ Wq, const float* __restrict__ Wk,
                       const float* __restrict__ Wv, const float* __restrict__ Wsk,
                       const float* __restrict__ We, const float* __restrict__ W1,
                       const float* __restrict__ Wp, const float* __restrict__ W_ih,
                       const float* __restrict__ W_hh,
                       const float* __restrict__ bq, const float* __restrict__ bk,
                       const float* __restrict__ bv, const float* __restrict__ bsk) {
    int bid = blockIdx.x, t = threadIdx.x;
    if (bid < PB_ZERO) {                                  // zero cnt
        int i = bid*256 + t;
        if (i < BB*NN) g_cnt[i] = 0;
        return;
    }
    bid -= PB_ZERO;
    if (bid < PB_GX) {                                    // gather node emb
        gather_body(g_x, emb, node_tokens, bid*4 + (t >> 6), t & 63);
        return;
    }
    bid -= PB_GX;
    if (bid < PB_GEA) {                                   // gather edge emb
        gather_body(g_ea, emb, edge_tokens, bid*4 + (t >> 6), t & 63);
        return;
    }
    bid -= PB_GEA;
    if (bid < 5*PB_CVT) {                                 // Wq/Wk/Wv/Wsk/We [256,1024]
        int w = bid / PB_CVT, r = bid % PB_CVT;
        const float* W = (w==0) ? Wq : (w==1) ? Wk : (w==2) ? Wv : (w==3) ? Wsk : We;
        __half* dst = (w==4) ? g_bE : (g_bN + (size_t)w*1024*DD);
        convT_body(W, dst, DD, HD, (r & 7)*32, (r >> 3)*32, t);
        return;
    }
    bid -= 5*PB_CVT;
    if (bid < PB_W1) {                                    // W1 [1024,256]
        convT_body(W1, g_bw1, HD, DD, (bid & 31)*32, (bid >> 5)*32, t);
        return;
    }
    bid -= PB_W1;
    if (bid < PB_WP) {                                    // Wp [256,256]
        convT_body(Wp, g_bwp, DD, DD, (bid & 7)*32, (bid >> 3)*32, t);
        return;
    }
    bid -= PB_WP;
    if (bid < PB_IH) {                                    // W_ih elementwise
        int i = bid*256 + t;
        g_bih[i] = __float2half_rn(W_ih[i]);
        return;
    }
    bid -= PB_IH;
    if (bid < PB_WHH) {                                   // pack W_hh (j8,g,8)
        int sub = t >> 5, j8 = t & 31;
        int g = bid*8 + sub;
        float4 a = *(const float4*)(W_hh + (size_t)g*DD + 8*j8);
        float4 b = *(const float4*)(W_hh + (size_t)g*DD + 8*j8 + 4);
        __half2 h0 = __floats2half2_rn(a.x, a.y);
        __half2 h1 = __floats2half2_rn(a.z, a.w);
        __half2 h2 = __floats2half2_rn(b.x, b.y);
        __half2 h3 = __floats2half2_rn(b.z, b.w);
        uint4 o;
        o.x = *reinterpret_cast<uint32_t*>(&h0);
        o.y = *reinterpret_cast<uint32_t*>(&h1);
        o.z = *reinterpret_cast<uint32_t*>(&h2);
        o.w = *reinterpret_cast<uint32_t*>(&h3);
        *(uint4*)(g_Wh8 + ((size_t)j8*G3 + g)*8) = o;
        return;
    }
    bid -= PB_WHH;
    {                                                     // bias concat
        int i = bid*256 + t;
        const float* src = (i < 1024) ? bq : (i < 2048) ? bk : (i < 3072) ? bv : bsk;
        g_biasN[i] = src[i & 1023];
    }
}
#define PREP_BLOCKS (PB_ZERO + PB_GX + PB_GEA + 5*PB_CVT + PB_W1 + PB_WP + PB_IH + PB_WHH + PB_BIAS)

// ================= single-pass fp16 mma GEMM core =================
#define KC 32
#define RSB 80
#define STG_A 0
#define STG_B 10240
#define STAGE_SZ 20480
#define NSTAGE 4
#define GEMM_SMEM (NSTAGE*STAGE_SZ)

template<int CRELU, int OUTMODE>
__device__ __forceinline__ void gemm_core(
    char* smc, const __half* __restrict__ A, const __half* __restrict__ Bw,
    const float* __restrict__ bias, float* __restrict__ C,
    __half* __restrict__ Ch, int Nld, int K, int bm, int bn) {
    const uint32_t smb = smem_to_u32(smc);
    const int t = threadIdx.x, lane = t & 31, warp = t >> 5;
    const int wm = (warp >> 2) * 64, wn = (warp & 3) * 32;

    const int fr = t >> 1, fk = (t & 1) * 16;
    const __half* Ap = A  + (size_t)(bm + fr) * K + fk;
    const __half* Bp = Bw + (size_t)(bn + fr) * K + fk;
    const uint32_t fillOff = smb + (uint32_t)(fr * RSB + fk * 2);

    const uint32_t aBase = smb + (uint32_t)(wm + (lane & 15)) * RSB + (uint32_t)(lane >> 4) * 16;
    const uint32_t bBase = smb + (uint32_t)(wn + ((lane >> 4) << 3) + (lane & 7)) * RSB
                               + (uint32_t)((lane >> 3) & 1) * 16;

    float acc[4][4][4];
#pragma unroll
    for (int i = 0; i < 4; i++)
#pragma unroll
        for (int j = 0; j < 4; j++)
#pragma unroll
            for (int k = 0; k < 4; k++) acc[i][j][k] = 0.f;

    const int NC = K / KC;
#pragma unroll
    for (int c = 0; c < NSTAGE - 1; c++) {
        uint32_t d = fillOff + (uint32_t)(c * STAGE_SZ);
        const __half* a0 = Ap + c * KC;
        const __half* b0 = Bp + c * KC;
        cpasync16(d + STG_A,      a0);
        cpasync16(d + STG_A + 16, a0 + 8);
        cpasync16(d + STG_B,      b0);
        cpasync16(d + STG_B + 16, b0 + 8);
        cp_commit();
    }

    for (int c = 0; c < NC; c++) {
        cp_wait<NSTAGE - 2>();
        __syncthreads();
        const uint32_t stg = (uint32_t)((c & (NSTAGE - 1)) * STAGE_SZ);
#pragma unroll
        for (int ks = 0; ks < 2; ks++) {
            const uint32_t kb = (uint32_t)(ks * 32);
            uint32_t br[2][4];
#pragma unroll
            for (int nb = 0; nb < 2; nb++)
                ldsm4(br[nb], bBase + stg + STG_B + (uint32_t)(nb * 16 * RSB) + kb);
            uint32_t ar[4][4];
#pragma unroll
            for (int mi = 0; mi < 4; mi++)
                ldsm4(ar[mi], aBase + stg + STG_A + (uint32_t)(mi * 16 * RSB) + kb);
#pragma unroll
            for (int mi = 0; mi < 4; mi++)
#pragma unroll
                for (int ni = 0; ni < 4; ni++)
                    mma16816h(acc[mi][ni], ar[mi][0], ar[mi][1], ar[mi][2], ar[mi][3],
                              br[ni>>1][(ni&1)*2], br[ni>>1][(ni&1)*2+1]);
        }
        __syncthreads();
        const int nx = c + NSTAGE - 1;
        if (nx < NC) {
            uint32_t d = fillOff + (uint32_t)((nx & (NSTAGE - 1)) * STAGE_SZ);
            const __half* a0 = Ap + nx * KC;
            const __half* b0 = Bp + nx * KC;
            cpasync16(d + STG_A,      a0);
            cpasync16(d + STG_A + 16, a0 + 8);
            cpasync16(d + STG_B,      b0);
            cpasync16(d + STG_B + 16, b0 + 8);
        }
        cp_commit();
    }

#pragma unroll
    for (int mi = 0; mi < 4; mi++) {
        const int r0 = bm + wm + mi*16 + (lane >> 2);
#pragma unroll
        for (int ni = 0; ni < 4; ni++) {
            const int col = bn + wn + ni*8 + (lane & 3)*2;
            float bx = 0.f, by = 0.f;
            if (bias) { bx = bias[col]; by = bias[col+1]; }
            float v0 = acc[mi][ni][0] + bx, v1 = acc[mi][ni][1] + by;
            float v2 = acc[mi][ni][2] + bx, v3 = acc[mi][ni][3] + by;
            if (CRELU) {
                v0 = fmaxf(v0, 0.f); v1 = fmaxf(v1, 0.f);
                v2 = fmaxf(v2, 0.f); v3 = fmaxf(v3, 0.f);
            }
            if (OUTMODE == 0) {
                *(float2*)(C + (size_t)r0 * Nld + col) = make_float2(v0, v1);
                *(float2*)(C + (size_t)(r0+8) * Nld + col) = make_float2(v2, v3);
            } else {
                __half2 p0 = __floats2half2_rn(v0, v1);
                __half2 p1 = __floats2half2_rn(v2, v3);
                *(uint32_t*)(Ch + (size_t)r0 * Nld + col) = *reinterpret_cast<uint32_t*>(&p0);
                *(uint32_t*)(Ch + (size_t)(r0+8) * Nld + col) = *reinterpret_cast<uint32_t*>(&p1);
            }
        }
    }
}

template<int CRELU, int OUTMODE>
__global__ __launch_bounds__(256, 1) void mmagemm_k(
    const __half* __restrict__ A, const __half* __restrict__ Bw,
    const float* __restrict__ bias, float* __restrict__ C,
    __half* __restrict__ Ch, int Nld, int K) {
    extern __shared__ char smc[];
    gemm_core<CRELU, OUTMODE>(smc, A, Bw, bias, C, Ch, Nld, K,
                              blockIdx.y * 128, blockIdx.x * 128);
}

// combined edge + qkvs GEMM (both fp16 out, K=256)
__global__ __launch_bounds__(256, 1) void gemm_big_k() {
    extern __shared__ char smc[];
    int cta = blockIdx.x;
    if (cta < 4000) {
        gemm_core<0, 1>(smc, g_ea, g_bE, nullptr, nullptr, g_e,
                        HD, DD, (cta >> 3) * 128, (cta & 7) * 128);
    } else {
        int r = cta - 4000;
        gemm_core<0, 1>(smc, g_x, g_bN, g_biasN, nullptr, g_qkvs,
                        QKVS_W, DD, (r >> 5) * 128, (r & 31) * 128);
    }
}

// ================= CSR build over dst =================
__global__ void count_k(const int* __restrict__ ei) {
    int i = blockIdx.x * blockDim.x + threadIdx.x;
    if (i >= BB*EE) return;
    int b = i / EE, e = i % EE;
    int dst = ei[(b*2 + 1)*EE + e];
    atomicAdd(&g_cnt[b*NN + dst], 1);
}
__global__ void scan_k() {   // grid BB, block 1024
    __shared__ int s[1024];
    int b = blockIdx.x, t = threadIdx.x;
    int v = (t < NN) ? g_cnt[b*NN + t] : 0;
    s[t] = v;
    __syncthreads();
    for (int d = 1; d < 1024; d <<= 1) {
        int x = (t >= d) ? s[t - d] : 0;
        __syncthreads();
        s[t] += x;
        __syncthreads();
    }
    if (t < NN) {
        int excl = s[t] - v;
        g_off[b*NN + t] = excl;
        g_cur[b*NN + t] = excl;
    }
}
__global__ void fill_k(const int* __restrict__ ei) {
    int i = blockIdx.x * blockDim.x + threadIdx.x;
    if (i >= BB*EE) return;
    int b = i / EE, e = i % EE;
    int dst = ei[(b*2 + 1)*EE + e];
    int pos = atomicAdd(&g_cur[b*NN + dst], 1);
    g_eord[b*EE + pos] = e;
}

// ================= fused attention: uint4 loads + index prefetch =================
__global__ void attn_fused_k(const int* __restrict__ ei) {
    int g = blockIdx.x * 4 + (threadIdx.x >> 5);
    int lane = threadIdx.x & 31;
    if (g >= BB*NN*NH) return;
    int h = g & 3, bn = g >> 2;
    int b = bn / NN;
    int deg = g_cnt[bn], off = g_off[bn];
    const int off_b = b*EE + off;
    const int* srcRow = ei + (b*2)*EE;

    const __half* qp = g_qkvs + (size_t)bn*QKVS_W + h*DD + 8*lane;
    float q[8];
    unpack8(*(const uint4*)qp, q);

    float m = -3.0e38f, den = 0.f;
    float o[8];
#pragma unroll
    for (int r = 0; r < 8; r++) o[r] = 0.f;

    int e_cur = 0, s_cur = 0;
    if (deg > 0) { e_cur = g_eord[off_b]; s_cur = srcRow[e_cur]; }
    for (int i = 0; i < deg; i++) {
        int e_nxt = 0, s_nxt = 0;
        if (i + 1 < deg) { e_nxt = g_eord[off_b + i + 1]; s_nxt = srcRow[e_nxt]; }
        const __half* base = g_qkvs + (size_t)(b*NN + s_cur)*QKVS_W + h*DD + 8*lane;
        uint4 kw = *(const uint4*)(base + HD);
        uint4 vw = *(const uint4*)(base + 2*HD);
        uint4 ew = *(const uint4*)(g_e + (size_t)(b*EE + e_cur)*HD + h*DD + 8*lane);
        float kf[8], vf[8], ef[8];
        unpack8(kw, kf); unpack8(vw, vf); unpack8(ew, ef);
        float a = 0.f;
#pragma unroll
        for (int r = 0; r < 8; r++) a += q[r] * (kf[r] + ef[r]);
#pragma unroll
        for (int dlt = 16; dlt; dlt >>= 1) a += __shfl_xor_sync(0xffffffffu, a, dlt);
        a *= 0.0625f;
        float mn = fmaxf(m, a);
        float scale = expf(m - mn);
        float w = expf(a - mn);
        den = den * scale + w;
#pragma unroll
        for (int r = 0; r < 8; r++) o[r] = o[r] * scale + w * (vf[r] + ef[r]);
        m = mn;
        e_cur = e_nxt; s_cur = s_nxt;
    }
    float invden = (deg > 0) ? (1.f / den) : 0.f;
    const __half* sp = g_qkvs + (size_t)bn*QKVS_W + 3*HD + h*DD + 8*lane;
    float sk[8];
    unpack8(*(const uint4*)sp, sk);
    __half2 hv[4];
#pragma unroll
    for (int r = 0; r < 4; r++) {
        float f0 = fmaxf(sk[2*r]   + o[2*r]   * invden, 0.f);
        float f1 = fmaxf(sk[2*r+1] + o[2*r+1] * invden, 0.f);
        hv[r] = __floats2half2_rn(f0, f1);
    }
    *(uint4*)(g_h + (size_t)bn*HD + h*DD + 8*lane) = *reinterpret_cast<uint4*>(hv);
}

// ================= inv path =================
__global__ void mixed_inv_k(const int* __restrict__ tok, const int* __restrict__ nod,
                            const float* __restrict__ emb) {
    int row = blockIdx.x, t = threadIdx.x;   // 128 threads
    int b = row / LL;
    int tk = tok[row], nd = nod[row];
    float2 f0 = *(const float2*)(emb + (size_t)tk*DD + 2*t);
    float2 f1 = *(const float2*)(g_gr + (size_t)(b*NN + nd)*DD + 2*t);
    __half2 hv = __floats2half2_rn(f0.x + f1.x, f0.y + f1.y);
    *(uint32_t*)(g_inve + (size_t)row*DD + 2*t) = *reinterpret_cast<uint32_t*>(&hv);
}

// GRU: one block per batch, 384 threads, 2 gates/thread, W_hh fp16 packed
__global__ void gru_k(const float* __restrict__ b_hh) {
    __shared__ float hs[256];
    __shared__ float ghs[768];
    int b = blockIdx.x, t = threadIdx.x;  // 384 threads
    if (t < 256) hs[t] = 0.f;
    float bh0 = b_hh[t], bh1 = b_hh[t + 384];
    const uint4* W = (const uint4*)g_Wh8;
    __syncthreads();
    for (int l = 0; l < LL; l++) {
        float acc0 = bh0, acc1 = bh1;
#pragma unroll 8
        for (int j8 = 0; j8 < 32; j8++) {
            uint4 w0 = W[j8 * G3 + t];
            uint4 w1 = W[j8 * G3 + t + 384];
            float4 h0 = *(const float4*)(hs + 8*j8);
            float4 h1 = *(const float4*)(hs + 8*j8 + 4);
            float2 p;
            p = __half22float2(*reinterpret_cast<__half2*>(&w0.x));
            acc0 += h0.x*p.x + h0.y*p.y;
            p = __half22float2(*reinterpret_cast<__half2*>(&w0.y));
            acc0 += h0.z*p.x + h0.w*p.y;
            p = __half22float2(*reinterpret_cast<__half2*>(&w0.z));
            acc0 += h1.x*p.x + h1.y*p.y;
            p = __half22float2(*reinterpret_cast<__half2*>(&w0.w));
            acc0 += h1.z*p.x + h1.w*p.y;
            p = __half22float2(*reinterpret_cast<__half2*>(&w1.x));
            acc1 += h0.x*p.x + h0.y*p.y;
            p = __half22float2(*reinterpret_cast<__half2*>(&w1.y));
            acc1 += h0.z*p.x + h0.w*p.y;
            p = __half22float2(*reinterpret_cast<__half2*>(&w1.z));
            acc1 += h1.x*p.x + h1.y*p.y;
            p = __half22float2(*reinterpret_cast<__half2*>(&w1.w));
            acc1 += h1.z*p.x + h1.w*p.y;
        }
        ghs[t] = acc0;
        ghs[t + 384] = acc1;
        __syncthreads();
        float hn = 0.f;
        if (t < 256) {
            const float* g = g_gx + (size_t)(b*LL + l)*G3;
            float r = 1.f / (1.f + expf(-(g[t]       + ghs[t])));
            float z = 1.f / (1.f + expf(-(g[256 + t] + ghs[256 + t])));
            float c = tanhf(g[512 + t] + r * ghs[512 + t]);
            hn = (1.f - z) * c + z * hs[t];
        }
        __syncthreads();
        if (t < 256) hs[t] = hn;
        __syncthreads();
    }
    if (t < 256) g_invvec[b*OO + t] = hs[t];
}

// ================= scoring =================
__global__ void score_k(const float* __restrict__ Wap, const float* __restrict__ bap,
                        const float* __restrict__ Wab, const float* __restrict__ bab,
                        const int* __restrict__ aa_token, const int* __restrict__ aa_node,
                        const float* __restrict__ mask, const float* __restrict__ emb,
                        float* __restrict__ out) {
    __shared__ float invs[256];
    __shared__ float u[256];
    __shared__ float red[256];
    int b = blockIdx.x, t = threadIdx.x;
    int warp = t >> 5, lane = t & 31;
    invs[t] = g_invvec[b*OO + t];
    __syncthreads();
    for (int d = warp*32; d < warp*32 + 32; d++) {
        float acc = 0.f;
#pragma unroll
        for (int r = 0; r < 8; r++) {
            int o = lane + 32*r;
            acc += Wap[(size_t)d*OO + o] * invs[o];
        }
#pragma unroll
        for (int dd = 16; dd; dd >>= 1) acc += __shfl_xor_sync(0xffffffffu, acc, dd);
        if (lane == 0) u[d] = acc + Wab[d];
    }
    red[t] = bap[t] * invs[t];
    __syncthreads();
    for (int s = 128; s; s >>= 1) {
        if (t < s) red[t] += red[t + s];
        __syncthreads();
    }
    float cb = red[0] + bab[0];
    for (int a = warp; a < ACT; a += 8) {
        int tok = aa_token[b*ACT + a], nod = aa_node[b*ACT + a];
        const float* er = emb + (size_t)tok*DD;
        const float* gg = g_gr + (size_t)(b*NN + nod)*DD;
        float acc = 0.f;
#pragma unroll
        for (int r = 0; r < 8; r++) {
            int d = lane + 32*r;
            acc += (er[d] + gg[d]) * u[d];
        }
#pragma unroll
        for (int dd = 16; dd; dd >>= 1) acc += __shfl_xor_sync(0xffffffffu, acc, dd);
        if (lane == 0) {
            float mk = mask[b*ACT + a];
            float lm = fmaxf(logf(mk), -FLT_MAX);
            out[b*ACT + a] = acc + cb + lm;
        }
    }
}

// ================= host launcher =================
extern "C" void kernel_launch(void* const* d_in, const int* in_sizes, int n_in,
                              void* d_out, int out_size) {
    const int*   node_tokens = (const int*)d_in[0];
    const int*   edge_tokens = (const int*)d_in[1];
    const int*   edge_index  = (const int*)d_in[2];
    const int*   inv_token   = (const int*)d_in[3];
    const int*   inv_node    = (const int*)d_in[4];
    const int*   aa_token    = (const int*)d_in[5];
    const int*   aa_node     = (const int*)d_in[6];
    const float* action_mask = (const float*)d_in[7];
    const float* emb         = (const float*)d_in[8];
    const float* Wq  = (const float*)d_in[9];
    const float* bq  = (const float*)d_in[10];
    const float* Wk  = (const float*)d_in[11];
    const float* bk  = (const float*)d_in[12];
    const float* Wv  = (const float*)d_in[13];
    const float* bv  = (const float*)d_in[14];
    const float* We  = (const float*)d_in[15];
    const float* Wsk = (const float*)d_in[16];
    const float* bsk = (const float*)d_in[17];
    const float* W1  = (const float*)d_in[18];
    const float* b1  = (const float*)d_in[19];
    const float* Wp  = (const float*)d_in[20];
    const float* bp  = (const float*)d_in[21];
    const float* W_ih = (const float*)d_in[22];
    const float* W_hh = (const float*)d_in[23];
    const float* b_ih = (const float*)d_in[24];
    const float* b_hh = (const float*)d_in[25];
    const float* Wab = (const float*)d_in[26];
    const float* bab = (const float*)d_in[27];
    const float* Wap = (const float*)d_in[28];
    const float* bap = (const float*)d_in[29];
    float* out = (float*)d_out;

    void* p;
    __half *h_, *inve_, *invh_, *bw1, *bwp, *bih;
    float *gr_, *gx_;
    cudaGetSymbolAddress(&p, g_h);     h_ = (__half*)p;
    cudaGetSymbolAddress(&p, g_gr);    gr_ = (float*)p;
    cudaGetSymbolAddress(&p, g_inve);  inve_ = (__half*)p;
    cudaGetSymbolAddress(&p, g_invh);  invh_ = (__half*)p;
    cudaGetSymbolAddress(&p, g_gx);    gx_ = (float*)p;
    cudaGetSymbolAddress(&p, g_bw1);   bw1 = (__half*)p;
    cudaGetSymbolAddress(&p, g_bwp);   bwp = (__half*)p;
    cudaGetSymbolAddress(&p, g_bih);   bih = (__half*)p;

    cudaFuncSetAttribute(gemm_big_k,      cudaFuncAttributeMaxDynamicSharedMemorySize, GEMM_SMEM);
    cudaFuncSetAttribute(mmagemm_k<1,0>,  cudaFuncAttributeMaxDynamicSharedMemorySize, GEMM_SMEM);
    cudaFuncSetAttribute(mmagemm_k<1,1>,  cudaFuncAttributeMaxDynamicSharedMemorySize, GEMM_SMEM);
    cudaFuncSetAttribute(mmagemm_k<0,0>,  cudaFuncAttributeMaxDynamicSharedMemorySize, GEMM_SMEM);

    // 1: all gathers + weight conversions + cnt zero, one launch
    prep_k<<<PREP_BLOCKS, 256>>>(node_tokens, edge_tokens, emb,
                                 Wq, Wk, Wv, Wsk, We, W1, Wp, W_ih, W_hh,
                                 bq, bk, bv, bsk);
    // 2-4: CSR
    count_k<<<(BB*EE + 255)/256, 256>>>(edge_index);
    scan_k<<<BB, 1024>>>();
    fill_k<<<(BB*EE + 255)/256, 256>>>(edge_index);
    // 5: combined edge + qkvs GEMM
    gemm_big_k<<<8000, 256, GEMM_SMEM>>>();
    // 6: fused attention + skip + relu -> fp16 h
    attn_fused_k<<<(BB*NN*NH + 3)/4, 128>>>(edge_index);
    // 7: graph_repr = relu(h@W1 + b1) -> fp32
    dim3 ggr(DD/128, (BB*NN)/128);
    mmagemm_k<1,0><<<ggr, 256, GEMM_SMEM>>>(h_, bw1, b1, gr_, nullptr, DD, HD);
    // 8-11: inv path
    mixed_inv_k<<<BB*LL, 128>>>(inv_token, inv_node, emb);
    dim3 ginv(DD/128, (BB*LL)/128);
    mmagemm_k<1,1><<<ginv, 256, GEMM_SMEM>>>(inve_, bwp, bp, nullptr, invh_, DD, DD);
    dim3 ggx(G3/128, (BB*LL)/128);
    mmagemm_k<0,0><<<ggx, 256, GEMM_SMEM>>>(invh_, bih, b_ih, gx_, nullptr, G3, DD);
    gru_k<<<BB, 384>>>(b_hh);
    // 12: scores
    score_k<<<BB, 256>>>(Wap, bap, Wab, bab, aa_token, aa_node, action_mask, emb, out);
    (void)in_sizes; (void)n_in; (void)out_size;
}